// round 9
// baseline (speedup 1.0000x reference)
#include <cuda_runtime.h>
#include <math.h>

#define BMAX 2048

// ---------------- device scratch (no allocations allowed) ----------------
__device__ float g_rel[256];            // 16x16 isometry
__device__ float g_W[256];              // expm(-sym(bias_spd)/2)
__device__ float g_Ybg[400];            // cayley(bias_gr) 20x20
__device__ float g_X[2][BMAX][256];     // SPD chain results (0=q,1=a)
__device__ float g_C[2][BMAX][200];     // GR 20x10 panels   (0=q,1=a)

// =====================================================================
// Kernel 0: one-block precompute of batch-invariant matrices
// =====================================================================
__global__ void precompute_kernel(const float* __restrict__ ref_params,
                                  const float* __restrict__ bias_spd,
                                  const float* __restrict__ bias_gr)
{
    __shared__ float Bs[256], E[256];
    __shared__ float A20[400];
    __shared__ float Aug[20][40];
    __shared__ float prow[40], fcol[20];
    __shared__ float pv;

    const int tid = threadIdx.x;
    const int i = tid >> 4, j = tid & 15;

    // ---- rel = prod of 120 Givens rotations, each lane owns one row ----
    if (tid < 16) {
        float row[16];
        #pragma unroll
        for (int c = 0; c < 16; c++) row[c] = (c == tid) ? 1.f : 0.f;
        int m = 0;
        for (int pi = 0; pi < 16; pi++) {
            for (int pj = pi + 1; pj < 16; pj++) {
                float ang = ref_params[m++];
                float c = cosf(ang), s = sinf(ang);
                float a = row[pi], b = row[pj];
                row[pi] = c * a + s * b;
                row[pj] = -s * a + c * b;
            }
        }
        #pragma unroll
        for (int c = 0; c < 16; c++) g_rel[tid * 16 + c] = row[c];
    }

    // ---- W = expm(-0.25*(bias+bias^T)) via scaling(2^-7) + Taylor-8 ----
    {
        float v = -0.25f * (bias_spd[i * 16 + j] + bias_spd[j * 16 + i]);
        Bs[tid] = v * (1.0f / 128.0f);
        E[tid]  = (i == j) ? 1.f : 0.f;
    }
    __syncthreads();
    for (int k = 8; k >= 1; k--) {
        float a = 0.f;
        #pragma unroll
        for (int kk = 0; kk < 16; kk++) a += Bs[i * 16 + kk] * E[kk * 16 + j];
        __syncthreads();
        E[tid] = ((i == j) ? 1.f : 0.f) + a * (1.0f / (float)k);
        __syncthreads();
    }
    for (int q = 0; q < 7; q++) {
        float a = 0.f;
        #pragma unroll
        for (int kk = 0; kk < 16; kk++) a += E[i * 16 + kk] * E[kk * 16 + j];
        __syncthreads();
        E[tid] = a;
        __syncthreads();
    }
    g_W[tid] = E[tid];

    // ---- Ybg = (I - A)(I + A)^{-1}, A = skew(bias_gr) 20x20 ----
    for (int e = tid; e < 400; e += 256) {
        int ii = e / 20, jj = e % 20;
        float v = 0.f;
        if (ii < 10 && jj >= 10)      v =  bias_gr[ii * 10 + (jj - 10)];
        else if (ii >= 10 && jj < 10) v = -bias_gr[jj * 10 + (ii - 10)];
        A20[e] = v;
    }
    __syncthreads();
    for (int e = tid; e < 800; e += 256) {
        int ii = e / 40, jj = e % 40;
        float v;
        if (jj < 20) v = ((ii == jj) ? 1.f : 0.f) + A20[ii * 20 + jj];
        else         v = ((jj - 20) == ii) ? 1.f : 0.f;
        Aug[ii][jj] = v;
    }
    __syncthreads();
    for (int p = 0; p < 20; p++) {
        if (tid == 0) pv = Aug[p][p];
        __syncthreads();
        if (tid < 40) prow[tid] = Aug[p][tid] / pv;
        if (tid >= 64 && tid < 84) {
            int r = tid - 64;
            fcol[r] = (r == p) ? 0.f : Aug[r][p];
        }
        __syncthreads();
        for (int e = tid; e < 800; e += 256) {
            int ii = e / 40, jj = e % 40;
            Aug[ii][jj] = (ii == p) ? prow[jj] : Aug[ii][jj] - fcol[ii] * prow[jj];
        }
        __syncthreads();
    }
    for (int e = tid; e < 400; e += 256) {
        int ii = e / 20, jj = e % 20;
        float a = 0.f;
        #pragma unroll
        for (int k = 0; k < 20; k++) {
            float l = ((ii == k) ? 1.f : 0.f) - A20[ii * 20 + k];
            a += l * Aug[k][jj + 20];
        }
        g_Ybg[e] = a;
    }
}

// =====================================================================
// Kernel 1: SPD chains. grid (B, 2). Y = P * exp(x_last) * P^T
// =====================================================================
__global__ void spd_chain_kernel(const int* __restrict__ q_ids,
                                 const int* __restrict__ a_ids,
                                 const float* __restrict__ q_emb,
                                 const float* __restrict__ a_emb,
                                 int T)
{
    __shared__ float Es[256], As[256], A2[256], Sm[256], P[256], T1[256];
    const int b = blockIdx.x, table = blockIdx.y;
    const int* ids = table ? a_ids : q_ids;
    const float* emb = table ? a_emb : q_emb;
    const int tid = threadIdx.x;
    const int i = tid >> 4, j = tid & 15;

    for (int t = 0; t < T; t++) {
        int id = ids[b * T + t];
        Es[tid] = emb[(size_t)id * 256 + tid];
        __syncthreads();
        float scale = (t == T - 1) ? 0.5f : 0.25f; // sym()*1 or sym()*0.5
        As[tid] = scale * (Es[tid] + Es[j * 16 + i]);
        __syncthreads();
        float a2 = 0.f;
        #pragma unroll
        for (int k = 0; k < 16; k++) a2 += As[i * 16 + k] * As[k * 16 + j];
        A2[tid] = a2;
        __syncthreads();
        float a3 = 0.f;
        #pragma unroll
        for (int k = 0; k < 16; k++) a3 += A2[i * 16 + k] * As[k * 16 + j];
        Sm[tid] = ((i == j) ? 1.f : 0.f) + As[tid] + 0.5f * a2 + (1.0f / 6.0f) * a3;
        __syncthreads();

        if (t == 0) {
            P[tid] = Sm[tid];
            __syncthreads();
        } else if (t < T - 1) {
            float acc = 0.f;
            #pragma unroll
            for (int k = 0; k < 16; k++) acc += P[i * 16 + k] * Sm[k * 16 + j];
            __syncthreads();
            P[tid] = acc;
            __syncthreads();
        } else {
            float acc = 0.f;
            #pragma unroll
            for (int k = 0; k < 16; k++) acc += P[i * 16 + k] * Sm[k * 16 + j];
            T1[tid] = acc;
            __syncthreads();
            float y = 0.f;
            #pragma unroll
            for (int k = 0; k < 16; k++) y += T1[i * 16 + k] * P[j * 16 + k]; // * P^T
            g_X[table][b][tid] = y;
        }
    }
}

// =====================================================================
// Kernel 2: Grassmannian 20x10 panel chains. grid (B, 2), 128 threads.
//   apply y_t = I - 2A + 2A^2 - 2A^3 (block form) right-to-left.
// =====================================================================
__global__ void gr_chain_kernel(const int* __restrict__ q_ids,
                                const int* __restrict__ a_ids,
                                const float* __restrict__ q_emb,
                                const float* __restrict__ a_emb,
                                const float* __restrict__ trans,
                                int T)
{
    __shared__ float x[100], Mt[100], Mb[100], u[100], v[100], p[100], q2[100], w1[100], w2[100];
    const int b = blockIdx.x, table = blockIdx.y;
    const int* ids = table ? a_ids : q_ids;
    const float* emb = table ? a_emb : q_emb;
    const int tid = threadIdx.x;
    const int i = tid / 10, j = tid % 10;

    if (tid < 100) { Mt[tid] = (i == j) ? 1.f : 0.f; Mb[tid] = 0.f; }
    __syncthreads();

    for (int t = T - 1; t >= 0; t--) {
        int id = ids[b * T + t];
        if (tid < 100) {
            float e = emb[(size_t)id * 100 + tid];
            x[tid] = table ? e : trans[tid] * e;
        }
        __syncthreads();
        if (tid < 100) {
            float su = 0.f, sv = 0.f;
            #pragma unroll
            for (int k = 0; k < 10; k++) {
                su += x[i * 10 + k] * Mb[k * 10 + j];   // u = x @ Mb
                sv += x[k * 10 + i] * Mt[k * 10 + j];   // v = x^T @ Mt
            }
            u[tid] = su; v[tid] = sv;
        }
        __syncthreads();
        if (tid < 100) {
            float sp = 0.f, sq = 0.f;
            #pragma unroll
            for (int k = 0; k < 10; k++) {
                sp += x[k * 10 + i] * u[k * 10 + j];    // p = x^T @ u
                sq += x[i * 10 + k] * v[k * 10 + j];    // q2 = x @ v
            }
            p[tid] = sp; q2[tid] = sq;
        }
        __syncthreads();
        if (tid < 100) {
            float sw1 = 0.f, sw2 = 0.f;
            #pragma unroll
            for (int k = 0; k < 10; k++) {
                sw1 += x[i * 10 + k] * (v[k * 10 + j] - p[k * 10 + j]);  // x@(v-p)
                sw2 += x[k * 10 + i] * (u[k * 10 + j] + q2[k * 10 + j]); // x^T@(u+q2)
            }
            w1[tid] = sw1; w2[tid] = sw2;
        }
        __syncthreads();
        if (tid < 100) {
            Mt[tid] = Mt[tid] - 2.f * u[tid] - 2.f * w1[tid];
            Mb[tid] = Mb[tid] + 2.f * v[tid] - 2.f * w2[tid];
        }
        __syncthreads();
    }
    if (tid < 100) {
        g_C[table][b][tid]       = Mt[tid]; // rows 0..9
        g_C[table][b][100 + tid] = Mb[tid]; // rows 10..19
    }
}

// =====================================================================
// Kernel 3: per-B finalize: rel-conj, Newton-Schulz inv-sqrt, Jacobi
// eigenvalues, Grassmannian distance, combine.
// =====================================================================
__global__ void finalize_kernel(float* __restrict__ out,
                                const float* __restrict__ wf,
                                const float* __restrict__ wb)
{
    __shared__ float B0[256], B1[256], B2[256], B3[256], B4[256], Wc[256];
    __shared__ float Ybg[400], Cq[200], Ca[200], Q1[200], sq[100], red[16];
    __shared__ int   part[16];
    __shared__ float cj[16], bj[16];
    __shared__ float dspd_sh;

    const int b = blockIdx.x, tid = threadIdx.x;
    const int i = tid >> 4, j = tid & 15;

    // ---- load ----
    B0[tid] = g_X[0][b][tid];   // Xq
    B1[tid] = g_rel[tid];
    Wc[tid] = g_W[tid];
    for (int e = tid; e < 400; e += 256) Ybg[e] = g_Ybg[e];
    if (tid < 200) { Cq[tid] = g_C[0][b][tid]; Ca[tid] = g_C[1][b][tid]; }
    __syncthreads();

    // ---- X = rel @ Xq @ rel^T ----
    float acc = 0.f;
    #pragma unroll
    for (int k = 0; k < 16; k++) acc += B1[i * 16 + k] * B0[k * 16 + j];
    B2[tid] = acc;
    __syncthreads();
    acc = 0.f;
    #pragma unroll
    for (int k = 0; k < 16; k++) acc += B2[i * 16 + k] * B1[j * 16 + k];
    __syncthreads();
    B2[tid] = acc;                       // Y0 = X
    B3[tid] = (i == j) ? 1.f : 0.f;      // Z0 = I
    __syncthreads();

    // ---- Newton-Schulz: Z -> X^{-1/2} ----
    for (int it = 0; it < 7; it++) {
        float t = 0.f;
        #pragma unroll
        for (int k = 0; k < 16; k++) t += B3[i * 16 + k] * B2[k * 16 + j]; // Z@Y
        __syncthreads();
        B4[tid] = ((i == j) ? 1.5f : 0.f) - 0.5f * t;                      // G
        __syncthreads();
        float yn = 0.f, zn = 0.f;
        #pragma unroll
        for (int k = 0; k < 16; k++) {
            yn += B2[i * 16 + k] * B4[k * 16 + j];   // Y@G
            zn += B4[i * 16 + k] * B3[k * 16 + j];   // G@Z
        }
        __syncthreads();
        B2[tid] = yn; B3[tid] = zn;
        __syncthreads();
    }

    // ---- m = W @ (Z @ Xa @ Z) @ W ----
    B0[tid] = g_X[1][b][tid];            // Xa
    __syncthreads();
    acc = 0.f;
    #pragma unroll
    for (int k = 0; k < 16; k++) acc += B3[i * 16 + k] * B0[k * 16 + j];
    B1[tid] = acc; __syncthreads();
    acc = 0.f;
    #pragma unroll
    for (int k = 0; k < 16; k++) acc += B1[i * 16 + k] * B3[k * 16 + j];
    B2[tid] = acc; __syncthreads();
    acc = 0.f;
    #pragma unroll
    for (int k = 0; k < 16; k++) acc += Wc[i * 16 + k] * B2[k * 16 + j];
    B1[tid] = acc; __syncthreads();
    acc = 0.f;
    #pragma unroll
    for (int k = 0; k < 16; k++) acc += B1[i * 16 + k] * Wc[k * 16 + j];
    __syncthreads();
    B0[tid] = acc;                       // m
    __syncthreads();

    // ---- parallel Jacobi eigenvalues (values only) ----
    for (int sweep = 0; sweep < 10; sweep++) {
        for (int r = 0; r < 15; r++) {
            if (tid < 8) {
                int pI, qI;
                if (tid == 0) { pI = 0; qI = 1 + ((14 + r) % 15); }
                else { pI = 1 + ((tid - 1 + r) % 15); qI = 1 + ((14 - tid + r) % 15); }
                float app = B0[pI * 16 + pI], aqq = B0[qI * 16 + qI], apq = B0[pI * 16 + qI];
                float c, s;
                if (fabsf(apq) < 1e-30f) { c = 1.f; s = 0.f; }
                else {
                    float tau = (aqq - app) / (2.f * apq);
                    float tt = (tau >= 0.f ? 1.f : -1.f) / (fabsf(tau) + sqrtf(1.f + tau * tau));
                    c = 1.0f / sqrtf(1.f + tt * tt); s = tt * c;
                }
                part[pI] = qI; part[qI] = pI;
                cj[pI] = c; cj[qI] = c;
                bj[pI] = -s; bj[qI] = s;
            }
            __syncthreads();
            float bv = cj[j] * B0[i * 16 + j] + bj[j] * B0[i * 16 + part[j]];
            B1[tid] = bv;
            __syncthreads();
            float av = cj[i] * B1[tid] + bj[i] * B1[part[i] * 16 + j];
            __syncthreads();
            B0[tid] = av;
            __syncthreads();
        }
    }
    if (tid < 16) {
        float d = B0[tid * 16 + tid];
        float l = logf(fmaxf(d, 1e-30f));
        red[tid] = l * l;
    }
    __syncthreads();
    if (tid == 0) {
        float s2 = 0.f;
        #pragma unroll
        for (int e = 0; e < 16; e++) s2 += red[e];
        dspd_sh = sqrtf(s2);
    }

    // ---- Grassmannian: Q1 = Ybg @ Cq ; s = ||Q1^T Ca||_F^2 ----
    if (tid < 200) {
        int ii = tid / 10, jj = tid % 10;
        float a = 0.f;
        #pragma unroll
        for (int k = 0; k < 20; k++) a += Ybg[ii * 20 + k] * Cq[k * 10 + jj];
        Q1[tid] = a;
    }
    __syncthreads();
    if (tid < 100) {
        int ii = tid / 10, jj = tid % 10;
        float a = 0.f;
        #pragma unroll
        for (int k = 0; k < 20; k++) a += Q1[k * 10 + ii] * Ca[k * 10 + jj];
        sq[tid] = a * a;
    }
    __syncthreads();
    if (tid == 0) {
        float s = 0.f;
        for (int e = 0; e < 100; e++) s += sq[e];
        float d_gr = sqrtf(fmaxf(20.f - 2.f * s, 0.f));
        out[b] = -wf[0] * (dspd_sh + d_gr) + wb[0];
    }
}

// =====================================================================
extern "C" void kernel_launch(void* const* d_in, const int* in_sizes, int n_in,
                              void* d_out, int out_size)
{
    const int*   q_ids      = (const int*)  d_in[0];
    const int*   a_ids      = (const int*)  d_in[1];
    const float* q_emb_spd  = (const float*)d_in[2];
    const float* a_emb_spd  = (const float*)d_in[3];
    const float* ref_params = (const float*)d_in[4];
    const float* bias_spd   = (const float*)d_in[5];
    const float* q_emb_gr   = (const float*)d_in[6];
    const float* a_emb_gr   = (const float*)d_in[7];
    const float* trans_gr   = (const float*)d_in[8];
    const float* bias_gr    = (const float*)d_in[9];
    const float* wf         = (const float*)d_in[10];
    const float* wb         = (const float*)d_in[11];
    float* out = (float*)d_out;

    int B = out_size;
    if (B > BMAX) B = BMAX;
    int T = in_sizes[0] / B;

    precompute_kernel<<<1, 256>>>(ref_params, bias_spd, bias_gr);
    spd_chain_kernel<<<dim3(B, 2), 256>>>(q_ids, a_ids, q_emb_spd, a_emb_spd, T);
    gr_chain_kernel<<<dim3(B, 2), 128>>>(q_ids, a_ids, q_emb_gr, a_emb_gr, trans_gr, T);
    finalize_kernel<<<B, 256>>>(out, wf, wb);
}

// round 10
// speedup vs baseline: 2.2170x; 2.2170x over previous
#include <cuda_runtime.h>
#include <math.h>

#define BMAX 2048
#define NS_ITERS 5
#define JAC_SWEEPS 8

// ---------------- device scratch (no allocations allowed) ----------------
__device__ float g_rel[256];            // 16x16 isometry
__device__ float g_W[256];              // expm(-sym(bias_spd)/2)
__device__ float g_Ybg[400];            // cayley(bias_gr) 20x20
__device__ float g_X[2][BMAX][256];     // SPD chain results (0=q,1=a)
__device__ float g_dgr[BMAX];           // per-batch Grassmannian distance

// =====================================================================
// warp-level 16x16 helpers. Layout: lane = 2*r + cpar, lane owns row r,
// cols c0..c0+7 (c0 = cpar*8), 8 floats in registers. Smem tiles are
// row-major with stride 20 floats (80B, 16B-aligned rows).
// =====================================================================
__device__ __forceinline__ void fullrow16(const float h[8], int cpar, float a[16]) {
    #pragma unroll
    for (int i = 0; i < 8; i++) {
        float o = __shfl_xor_sync(0xffffffffu, h[i], 1);
        a[i]     = cpar ? o    : h[i];
        a[8 + i] = cpar ? h[i] : o;
    }
}

// C(half-row) = a(full row) @ B(smem, stride 20)
__device__ __forceinline__ void wmm16(const float a[16], const float* Bs, int c0, float c[8]) {
    #pragma unroll
    for (int i = 0; i < 8; i++) c[i] = 0.f;
    #pragma unroll
    for (int k = 0; k < 16; k++) {
        float4 b0 = *(const float4*)(Bs + k * 20 + c0);
        float4 b1 = *(const float4*)(Bs + k * 20 + c0 + 4);
        float ak = a[k];
        c[0] += ak * b0.x; c[1] += ak * b0.y; c[2] += ak * b0.z; c[3] += ak * b0.w;
        c[4] += ak * b1.x; c[5] += ak * b1.y; c[6] += ak * b1.z; c[7] += ak * b1.w;
    }
}

// C(half-row) = a(full row) @ B^T (B rows in smem, stride 20)
__device__ __forceinline__ void wmm16t(const float a[16], const float* Bs, int c0, float c[8]) {
    #pragma unroll
    for (int i = 0; i < 8; i++) {
        const float* br = Bs + (c0 + i) * 20;
        float4 b0 = *(const float4*)(br);
        float4 b1 = *(const float4*)(br + 4);
        float4 b2 = *(const float4*)(br + 8);
        float4 b3 = *(const float4*)(br + 12);
        c[i] = a[0]*b0.x + a[1]*b0.y + a[2]*b0.z + a[3]*b0.w
             + a[4]*b1.x + a[5]*b1.y + a[6]*b1.z + a[7]*b1.w
             + a[8]*b2.x + a[9]*b2.y + a[10]*b2.z + a[11]*b2.w
             + a[12]*b3.x + a[13]*b3.y + a[14]*b3.z + a[15]*b3.w;
    }
}

__device__ __forceinline__ void stoh(float* Bs, int r, int c0, const float h[8]) {
    *(float4*)(Bs + r * 20 + c0)     = make_float4(h[0], h[1], h[2], h[3]);
    *(float4*)(Bs + r * 20 + c0 + 4) = make_float4(h[4], h[5], h[6], h[7]);
}

// =====================================================================
// Kernel 0: one-block precompute of batch-invariant matrices (unchanged,
// proven in the passing R8 kernel)
// =====================================================================
__global__ void precompute_kernel(const float* __restrict__ ref_params,
                                  const float* __restrict__ bias_spd,
                                  const float* __restrict__ bias_gr)
{
    __shared__ float Bs[256], E[256];
    __shared__ float A20[400];
    __shared__ float Aug[20][40];
    __shared__ float prow[40], fcol[20];
    __shared__ float pv;

    const int tid = threadIdx.x;
    const int i = tid >> 4, j = tid & 15;

    // ---- rel = prod of 120 Givens rotations, each lane owns one row ----
    if (tid < 16) {
        float row[16];
        #pragma unroll
        for (int c = 0; c < 16; c++) row[c] = (c == tid) ? 1.f : 0.f;
        int m = 0;
        for (int pi = 0; pi < 16; pi++) {
            for (int pj = pi + 1; pj < 16; pj++) {
                float ang = ref_params[m++];
                float c = cosf(ang), s = sinf(ang);
                float a = row[pi], b = row[pj];
                row[pi] = c * a + s * b;
                row[pj] = -s * a + c * b;
            }
        }
        #pragma unroll
        for (int c = 0; c < 16; c++) g_rel[tid * 16 + c] = row[c];
    }

    // ---- W = expm(-0.25*(bias+bias^T)) via scaling(2^-7) + Taylor-8 ----
    {
        float v = -0.25f * (bias_spd[i * 16 + j] + bias_spd[j * 16 + i]);
        Bs[tid] = v * (1.0f / 128.0f);
        E[tid]  = (i == j) ? 1.f : 0.f;
    }
    __syncthreads();
    for (int k = 8; k >= 1; k--) {
        float a = 0.f;
        #pragma unroll
        for (int kk = 0; kk < 16; kk++) a += Bs[i * 16 + kk] * E[kk * 16 + j];
        __syncthreads();
        E[tid] = ((i == j) ? 1.f : 0.f) + a * (1.0f / (float)k);
        __syncthreads();
    }
    for (int q = 0; q < 7; q++) {
        float a = 0.f;
        #pragma unroll
        for (int kk = 0; kk < 16; kk++) a += E[i * 16 + kk] * E[kk * 16 + j];
        __syncthreads();
        E[tid] = a;
        __syncthreads();
    }
    g_W[tid] = E[tid];

    // ---- Ybg = (I - A)(I + A)^{-1}, A = skew(bias_gr) 20x20 ----
    for (int e = tid; e < 400; e += 256) {
        int ii = e / 20, jj = e % 20;
        float v = 0.f;
        if (ii < 10 && jj >= 10)      v =  bias_gr[ii * 10 + (jj - 10)];
        else if (ii >= 10 && jj < 10) v = -bias_gr[jj * 10 + (ii - 10)];
        A20[e] = v;
    }
    __syncthreads();
    for (int e = tid; e < 800; e += 256) {
        int ii = e / 40, jj = e % 40;
        float v;
        if (jj < 20) v = ((ii == jj) ? 1.f : 0.f) + A20[ii * 20 + jj];
        else         v = ((jj - 20) == ii) ? 1.f : 0.f;
        Aug[ii][jj] = v;
    }
    __syncthreads();
    for (int p = 0; p < 20; p++) {
        if (tid == 0) pv = Aug[p][p];
        __syncthreads();
        if (tid < 40) prow[tid] = Aug[p][tid] / pv;
        if (tid >= 64 && tid < 84) {
            int r = tid - 64;
            fcol[r] = (r == p) ? 0.f : Aug[r][p];
        }
        __syncthreads();
        for (int e = tid; e < 800; e += 256) {
            int ii = e / 40, jj = e % 40;
            Aug[ii][jj] = (ii == p) ? prow[jj] : Aug[ii][jj] - fcol[ii] * prow[jj];
        }
        __syncthreads();
    }
    for (int e = tid; e < 400; e += 256) {
        int ii = e / 20, jj = e % 20;
        float a = 0.f;
        #pragma unroll
        for (int k = 0; k < 20; k++) {
            float l = ((ii == k) ? 1.f : 0.f) - A20[ii * 20 + k];
            a += l * Aug[k][jj + 20];
        }
        g_Ybg[e] = a;
    }
}

// =====================================================================
// Kernel 1: SPD chains, 1 warp per (b, table). Y = P * exp(x_last) * P^T,
// P = Sm_0 @ ... @ Sm_{T-2}, Sm = I + A + A^2/2 (Taylor-2, ||A||~3e-3).
// =====================================================================
__global__ void __launch_bounds__(256)
spd_chain_kernel(const int* __restrict__ q_ids, const int* __restrict__ a_ids,
                 const float* __restrict__ q_emb, const float* __restrict__ a_emb,
                 int B, int T)
{
    __shared__ float sb[8][640];
    const int w = threadIdx.x >> 5, lane = threadIdx.x & 31;
    const int gw = blockIdx.x * 8 + w;
    if (gw >= 2 * B) return;
    const int table = gw & 1, b = gw >> 1;
    const int* ids = table ? a_ids : q_ids;
    const float* emb = table ? a_emb : q_emb;
    const int r = lane >> 1, cpar = lane & 1, c0 = cpar * 8;
    float* bufA = sb[w];
    float* bufB = sb[w] + 320;

    float P[8];
    #pragma unroll
    for (int i = 0; i < 8; i++) P[i] = ((r >> 3) == cpar && (r & 7) == i) ? 1.f : 0.f;

    #pragma unroll 1
    for (int t = 0; t < T; t++) {
        int id = ids[b * T + t];
        const float* rp = emb + (size_t)id * 256 + r * 16 + c0;
        float4 e0 = *(const float4*)rp;
        float4 e1 = *(const float4*)(rp + 4);
        *(float4*)(bufA + r * 20 + c0)     = e0;
        *(float4*)(bufA + r * 20 + c0 + 4) = e1;
        __syncwarp();                                  // E visible; prior-token reads done
        const float scale = (t == T - 1) ? 0.5f : 0.25f;
        float er[8] = {e0.x, e0.y, e0.z, e0.w, e1.x, e1.y, e1.z, e1.w};
        float Ah[8];
        #pragma unroll
        for (int i = 0; i < 8; i++) Ah[i] = scale * (er[i] + bufA[(c0 + i) * 20 + r]);
        stoh(bufB, r, c0, Ah);
        __syncwarp();                                  // A visible
        float a16[16]; fullrow16(Ah, cpar, a16);
        float A2[8];  wmm16(a16, bufB, c0, A2);
        float Sm[8];
        #pragma unroll
        for (int i = 0; i < 8; i++) Sm[i] = Ah[i] + 0.5f * A2[i];
        if ((r >> 3) == cpar) Sm[r & 7] += 1.f;
        __syncwarp();                                  // A reads done
        stoh(bufB, r, c0, Sm);
        if (t == T - 1) stoh(bufA, r, c0, P);          // stash P for transpose
        __syncwarp();                                  // Sm (and P) visible
        float p16[16]; fullrow16(P, cpar, p16);
        float Pn[8];  wmm16(p16, bufB, c0, Pn);        // P @ Sm
        if (t < T - 1) {
            #pragma unroll
            for (int i = 0; i < 8; i++) P[i] = Pn[i];
        } else {
            float t16[16]; fullrow16(Pn, cpar, t16);
            float Y[8];   wmm16t(t16, bufA, c0, Y);    // (P@Exp) @ P^T
            *(float4*)(&g_X[table][b][r * 16 + c0])     = make_float4(Y[0], Y[1], Y[2], Y[3]);
            *(float4*)(&g_X[table][b][r * 16 + c0 + 4]) = make_float4(Y[4], Y[5], Y[6], Y[7]);
        }
    }
}

// =====================================================================
// Kernel 2: Grassmannian, 1 warp per b, both tables. Lane<20: column j of
// table tbl's 20x10 panel M (Mt=rows 0..9, Mb=rows 10..19) in registers.
// Cayley Taylor-2:  Mt -= 2(x@Mb) + 2(x x^T Mt);  Mb += 2(x^T Mt) - 2(x^T x Mb)
// Epilogue: d_gr = sqrt(20 - 2*||(Ybg@Cq)^T Ca||_F^2)  -> g_dgr[b]
// =====================================================================
__global__ void __launch_bounds__(256)
gr_chain_kernel(const int* __restrict__ q_ids, const int* __restrict__ a_ids,
                const float* __restrict__ q_emb, const float* __restrict__ a_emb,
                const float* __restrict__ trans, int B, int T)
{
    __shared__ float xs[8][240];     // [warp][2 tables][10 rows][12 (pad)]
    __shared__ float q1s[8][200];    // [warp][10 cols][20]
    __shared__ float YbgT[400];      // YbgT[k][i] = Ybg[i][k], stride 20
    __shared__ float transS[100];
    for (int e = threadIdx.x; e < 400; e += blockDim.x) {
        int ii = e / 20, kk = e - ii * 20;
        YbgT[kk * 20 + ii] = g_Ybg[e];
    }
    for (int e = threadIdx.x; e < 100; e += blockDim.x) transS[e] = trans[e];
    __syncthreads();

    const int w = threadIdx.x >> 5, lane = threadIdx.x & 31;
    const int b = blockIdx.x * 8 + w;
    if (b >= B) return;
    float* xw = xs[w];
    const int tbl = lane / 10;
    const int j = lane - tbl * 10;
    const bool active = lane < 20;

    float Mt[10], Mb[10];
    #pragma unroll
    for (int k = 0; k < 10; k++) { Mt[k] = (k == j && active) ? 1.f : 0.f; Mb[k] = 0.f; }

    #pragma unroll 1
    for (int t = T - 1; t >= 0; t--) {
        int qid = q_ids[b * T + t], aid = a_ids[b * T + t];
        __syncwarp();                                  // prior x reads done
        for (int e = lane; e < 100; e += 32) {
            int rr = e / 10, cc = e - rr * 10;
            xw[rr * 12 + cc]       = q_emb[(size_t)qid * 100 + e] * transS[e];
            xw[120 + rr * 12 + cc] = a_emb[(size_t)aid * 100 + e];
        }
        __syncwarp();                                  // x visible
        if (active) {
            const float* xb = xw + tbl * 120;
            float u[10], v[10], w1[10], w2[10];
            #pragma unroll
            for (int k = 0; k < 10; k++) { v[k] = 0.f; w2[k] = 0.f; }
            // pass 1: u[k] = <xrow_k, Mb>,  v += Mt[k]*xrow_k
            #pragma unroll
            for (int k = 0; k < 10; k++) {
                float4 r0 = *(const float4*)(xb + k * 12);
                float4 r1 = *(const float4*)(xb + k * 12 + 4);
                float4 r2 = *(const float4*)(xb + k * 12 + 8);
                float xr[10] = {r0.x,r0.y,r0.z,r0.w, r1.x,r1.y,r1.z,r1.w, r2.x,r2.y};
                float s = 0.f;
                #pragma unroll
                for (int c = 0; c < 10; c++) s += xr[c] * Mb[c];
                u[k] = s;
                float mtk = Mt[k];
                #pragma unroll
                for (int c = 0; c < 10; c++) v[c] += mtk * xr[c];
            }
            // pass 2: w1[k] = <xrow_k, v>,  w2 += u[k]*xrow_k
            #pragma unroll
            for (int k = 0; k < 10; k++) {
                float4 r0 = *(const float4*)(xb + k * 12);
                float4 r1 = *(const float4*)(xb + k * 12 + 4);
                float4 r2 = *(const float4*)(xb + k * 12 + 8);
                float xr[10] = {r0.x,r0.y,r0.z,r0.w, r1.x,r1.y,r1.z,r1.w, r2.x,r2.y};
                float s = 0.f;
                #pragma unroll
                for (int c = 0; c < 10; c++) s += xr[c] * v[c];
                w1[k] = s;
                float uk = u[k];
                #pragma unroll
                for (int c = 0; c < 10; c++) w2[c] += uk * xr[c];
            }
            #pragma unroll
            for (int k = 0; k < 10; k++) {
                Mt[k] = Mt[k] - 2.f * u[k] - 2.f * w1[k];
                Mb[k] = Mb[k] + 2.f * v[k] - 2.f * w2[k];
            }
        }
    }

    // ---- epilogue ----
    float* q1w = q1s[w];
    if (lane < 10) {                                   // table 0: Q1 = Ybg @ Cq (col j)
        float Q1[20];
        #pragma unroll
        for (int i = 0; i < 20; i++) Q1[i] = 0.f;
        #pragma unroll
        for (int k = 0; k < 20; k++) {
            float ck = (k < 10) ? Mt[k] : Mb[k - 10];
            const float* yr = YbgT + k * 20;
            float4 y0 = *(const float4*)yr,       y1 = *(const float4*)(yr + 4),
                   y2 = *(const float4*)(yr + 8), y3 = *(const float4*)(yr + 12),
                   y4 = *(const float4*)(yr + 16);
            Q1[0]+=ck*y0.x; Q1[1]+=ck*y0.y; Q1[2]+=ck*y0.z; Q1[3]+=ck*y0.w;
            Q1[4]+=ck*y1.x; Q1[5]+=ck*y1.y; Q1[6]+=ck*y1.z; Q1[7]+=ck*y1.w;
            Q1[8]+=ck*y2.x; Q1[9]+=ck*y2.y; Q1[10]+=ck*y2.z; Q1[11]+=ck*y2.w;
            Q1[12]+=ck*y3.x; Q1[13]+=ck*y3.y; Q1[14]+=ck*y3.z; Q1[15]+=ck*y3.w;
            Q1[16]+=ck*y4.x; Q1[17]+=ck*y4.y; Q1[18]+=ck*y4.z; Q1[19]+=ck*y4.w;
        }
        #pragma unroll
        for (int i = 0; i < 20; i += 4)
            *(float4*)(q1w + j * 20 + i) = make_float4(Q1[i], Q1[i+1], Q1[i+2], Q1[i+3]);
    }
    __syncwarp();
    float s_loc = 0.f;
    if (lane >= 10 && lane < 20) {                     // table 1: ||Q1^T Ca||^2 (col j)
        #pragma unroll
        for (int i = 0; i < 10; i++) {
            const float* qc = q1w + i * 20;
            float4 a0 = *(const float4*)qc,       a1 = *(const float4*)(qc + 4),
                   a2 = *(const float4*)(qc + 8), a3 = *(const float4*)(qc + 12),
                   a4 = *(const float4*)(qc + 16);
            float qv[20] = {a0.x,a0.y,a0.z,a0.w, a1.x,a1.y,a1.z,a1.w,
                            a2.x,a2.y,a2.z,a2.w, a3.x,a3.y,a3.z,a3.w,
                            a4.x,a4.y,a4.z,a4.w};
            float d = 0.f;
            #pragma unroll
            for (int k = 0; k < 20; k++) d += qv[k] * ((k < 10) ? Mt[k] : Mb[k - 10]);
            s_loc += d * d;
        }
    }
    #pragma unroll
    for (int o = 16; o; o >>= 1) s_loc += __shfl_xor_sync(0xffffffffu, s_loc, o);
    if (lane == 0) g_dgr[b] = sqrtf(fmaxf(20.f - 2.f * s_loc, 0.f));
}

// =====================================================================
// Kernel 3: finalize, 1 warp per b. rel-conj, Newton-Schulz X^{-1/2},
// m = W (Z Xa Z) W, warp Jacobi eigenvalues, combine with g_dgr.
// =====================================================================
__global__ void __launch_bounds__(256)
finalize_kernel(float* __restrict__ out, const float* __restrict__ wf,
                const float* __restrict__ wb, int B)
{
    __shared__ float sb[8][640];
    __shared__ float RelS[320], WS[320];
    __shared__ int   partS[8][16];
    for (int e = threadIdx.x; e < 256; e += blockDim.x) {
        RelS[(e >> 4) * 20 + (e & 15)] = g_rel[e];
        WS  [(e >> 4) * 20 + (e & 15)] = g_W[e];
    }
    __syncthreads();
    const int w = threadIdx.x >> 5, lane = threadIdx.x & 31;
    const int b = blockIdx.x * 8 + w;
    if (b >= B) return;
    const int r = lane >> 1, cpar = lane & 1, c0 = cpar * 8;
    float* bufA = sb[w];
    float* bufB = sb[w] + 320;

    // ---- X = Rel @ Xq @ Rel^T ----
    {
        float4 x0 = *(const float4*)(&g_X[0][b][r * 16 + c0]);
        float4 x1 = *(const float4*)(&g_X[0][b][r * 16 + c0 + 4]);
        float h[8] = {x0.x,x0.y,x0.z,x0.w, x1.x,x1.y,x1.z,x1.w};
        stoh(bufA, r, c0, h);
    }
    __syncwarp();
    float Y[8], Z[8];
    {
        const float* rr = RelS + r * 20;
        float4 r0 = *(const float4*)rr,       r1 = *(const float4*)(rr + 4),
               r2 = *(const float4*)(rr + 8), r3 = *(const float4*)(rr + 12);
        float a16[16] = {r0.x,r0.y,r0.z,r0.w, r1.x,r1.y,r1.z,r1.w,
                         r2.x,r2.y,r2.z,r2.w, r3.x,r3.y,r3.z,r3.w};
        float T1[8]; wmm16(a16, bufA, c0, T1);
        float t16[16]; fullrow16(T1, cpar, t16);
        wmm16t(t16, RelS, c0, Y);
    }
    #pragma unroll
    for (int i = 0; i < 8; i++) Z[i] = ((r >> 3) == cpar && (r & 7) == i) ? 1.f : 0.f;

    // ---- Newton-Schulz: Z -> X^{-1/2} ----
    #pragma unroll 1
    for (int it = 0; it < NS_ITERS; it++) {
        __syncwarp(); stoh(bufA, r, c0, Y); __syncwarp();
        float z16[16]; fullrow16(Z, cpar, z16);
        float G[8];   wmm16(z16, bufA, c0, G);          // Z@Y
        #pragma unroll
        for (int i = 0; i < 8; i++) G[i] = -0.5f * G[i];
        if ((r >> 3) == cpar) G[r & 7] += 1.5f;
        __syncwarp(); stoh(bufB, r, c0, G); __syncwarp();
        float y16[16]; fullrow16(Y, cpar, y16);
        float Yn[8];  wmm16(y16, bufB, c0, Yn);         // Y@G
        __syncwarp(); stoh(bufA, r, c0, Z); __syncwarp();
        float g16[16]; fullrow16(G, cpar, g16);
        float Zn[8];  wmm16(g16, bufA, c0, Zn);         // G@Z
        #pragma unroll
        for (int i = 0; i < 8; i++) { Y[i] = Yn[i]; Z[i] = Zn[i]; }
    }

    // ---- m = W @ (Z @ Xa @ Z) @ W ----
    {
        float4 x0 = *(const float4*)(&g_X[1][b][r * 16 + c0]);
        float4 x1 = *(const float4*)(&g_X[1][b][r * 16 + c0 + 4]);
        float xa[8] = {x0.x,x0.y,x0.z,x0.w, x1.x,x1.y,x1.z,x1.w};
        __syncwarp(); stoh(bufA, r, c0, xa); __syncwarp();
    }
    {
        float z16[16]; fullrow16(Z, cpar, z16);
        float U[8];  wmm16(z16, bufA, c0, U);           // Z@Xa
        __syncwarp(); stoh(bufA, r, c0, Z); __syncwarp();
        float u16[16]; fullrow16(U, cpar, u16);
        float K[8];  wmm16(u16, bufA, c0, K);           // (Z Xa) Z
        __syncwarp(); stoh(bufA, r, c0, K); __syncwarp();
        const float* wr = WS + r * 20;
        float4 w0 = *(const float4*)wr,       w1 = *(const float4*)(wr + 4),
               w2 = *(const float4*)(wr + 8), w3 = *(const float4*)(wr + 12);
        float wrow[16] = {w0.x,w0.y,w0.z,w0.w, w1.x,w1.y,w1.z,w1.w,
                          w2.x,w2.y,w2.z,w2.w, w3.x,w3.y,w3.z,w3.w};
        float V[8]; wmm16(wrow, bufA, c0, V);           // W@K
        float v16[16]; fullrow16(V, cpar, v16);
        float Mh[8]; wmm16(v16, WS, c0, Mh);            // (W K) W
        __syncwarp(); stoh(bufA, r, c0, Mh); __syncwarp();
    }

    // ---- warp-parallel Jacobi eigenvalues ----
    float* cjs = bufB;          // [16]
    float* bjs = bufB + 16;     // [16]
    #pragma unroll 1
    for (int sweep = 0; sweep < JAC_SWEEPS; sweep++) {
        #pragma unroll 1
        for (int rr = 0; rr < 15; rr++) {
            if (lane < 8) {
                int pI, qI;
                if (lane == 0) { pI = 0; qI = 1 + ((14 + rr) % 15); }
                else { pI = 1 + ((lane - 1 + rr) % 15); qI = 1 + ((14 - lane + rr) % 15); }
                float app = bufA[pI * 20 + pI], aqq = bufA[qI * 20 + qI], apq = bufA[pI * 20 + qI];
                float cc, ss;
                if (fabsf(apq) < 1e-30f) { cc = 1.f; ss = 0.f; }
                else {
                    float tau = (aqq - app) / (2.f * apq);
                    float tt = (tau >= 0.f ? 1.f : -1.f) / (fabsf(tau) + sqrtf(1.f + tau * tau));
                    cc = rsqrtf(1.f + tt * tt); ss = tt * cc;
                }
                partS[w][pI] = qI; partS[w][qI] = pI;
                cjs[pI] = cc; cjs[qI] = cc; bjs[pI] = -ss; bjs[qI] = ss;
            }
            __syncwarp();
            float nv[8];
            #pragma unroll
            for (int i = 0; i < 8; i++) {
                int cc_ = c0 + i; int pc = partS[w][cc_];
                nv[i] = cjs[cc_] * bufA[r * 20 + cc_] + bjs[cc_] * bufA[r * 20 + pc];
            }
            __syncwarp();
            #pragma unroll
            for (int i = 0; i < 8; i++) bufA[r * 20 + c0 + i] = nv[i];
            __syncwarp();
            float crv = cjs[r], brv = bjs[r]; int pr = partS[w][r];
            #pragma unroll
            for (int i = 0; i < 8; i++)
                nv[i] = crv * bufA[r * 20 + c0 + i] + brv * bufA[pr * 20 + c0 + i];
            __syncwarp();
            #pragma unroll
            for (int i = 0; i < 8; i++) bufA[r * 20 + c0 + i] = nv[i];
            __syncwarp();
        }
    }

    float acc = 0.f;
    if (lane < 16) {
        float d = bufA[lane * 20 + lane];
        float l = logf(fmaxf(d, 1e-30f));
        acc = l * l;
    }
    #pragma unroll
    for (int o = 8; o; o >>= 1) acc += __shfl_xor_sync(0xffffffffu, acc, o);
    if (lane == 0) out[b] = -wf[0] * (sqrtf(acc) + g_dgr[b]) + wb[0];
}

// =====================================================================
extern "C" void kernel_launch(void* const* d_in, const int* in_sizes, int n_in,
                              void* d_out, int out_size)
{
    const int*   q_ids      = (const int*)  d_in[0];
    const int*   a_ids      = (const int*)  d_in[1];
    const float* q_emb_spd  = (const float*)d_in[2];
    const float* a_emb_spd  = (const float*)d_in[3];
    const float* ref_params = (const float*)d_in[4];
    const float* bias_spd   = (const float*)d_in[5];
    const float* q_emb_gr   = (const float*)d_in[6];
    const float* a_emb_gr   = (const float*)d_in[7];
    const float* trans_gr   = (const float*)d_in[8];
    const float* bias_gr    = (const float*)d_in[9];
    const float* wf         = (const float*)d_in[10];
    const float* wb         = (const float*)d_in[11];
    float* out = (float*)d_out;

    int B = out_size;
    if (B > BMAX) B = BMAX;
    int T = in_sizes[0] / B;

    precompute_kernel<<<1, 256>>>(ref_params, bias_spd, bias_gr);
    spd_chain_kernel<<<(2 * B + 7) / 8, 256>>>(q_ids, a_ids, q_emb_spd, a_emb_spd, B, T);
    gr_chain_kernel<<<(B + 7) / 8, 256>>>(q_ids, a_ids, q_emb_gr, a_emb_gr, trans_gr, B, T);
    finalize_kernel<<<(B + 7) / 8, 256>>>(out, wf, wb, B);
}

// round 11
// speedup vs baseline: 2.7825x; 1.2551x over previous
#include <cuda_runtime.h>
#include <math.h>

#define BMAX 2048
#define NS_ITERS 4
#define JAC_SWEEPS 6

// ---------------- device scratch (no allocations allowed) ----------------
__device__ float g_rel[256];            // 16x16 isometry
__device__ float g_W[256];              // expm(-sym(bias_spd)/2)
__device__ float g_Ybg[400];            // cayley(bias_gr) 20x20
__device__ float g_X[2][BMAX][256];     // SPD chain results (0=q,1=a)
__device__ float g_dgr[BMAX];           // per-batch Grassmannian distance

// =====================================================================
// warp-level 16x16 helpers. Layout: lane = 2*r + cpar, lane owns row r,
// cols c0..c0+7 (c0 = cpar*8). Smem tiles row-major, stride 20 floats.
// =====================================================================
__device__ __forceinline__ void fullrow16(const float h[8], int cpar, float a[16]) {
    #pragma unroll
    for (int i = 0; i < 8; i++) {
        float o = __shfl_xor_sync(0xffffffffu, h[i], 1);
        a[i]     = cpar ? o    : h[i];
        a[8 + i] = cpar ? h[i] : o;
    }
}

// C(half-row) = a(full row) @ B(smem, stride 20)
__device__ __forceinline__ void wmm16(const float a[16], const float* Bs, int c0, float c[8]) {
    #pragma unroll
    for (int i = 0; i < 8; i++) c[i] = 0.f;
    #pragma unroll
    for (int k = 0; k < 16; k++) {
        float4 b0 = *(const float4*)(Bs + k * 20 + c0);
        float4 b1 = *(const float4*)(Bs + k * 20 + c0 + 4);
        float ak = a[k];
        c[0] += ak * b0.x; c[1] += ak * b0.y; c[2] += ak * b0.z; c[3] += ak * b0.w;
        c[4] += ak * b1.x; c[5] += ak * b1.y; c[6] += ak * b1.z; c[7] += ak * b1.w;
    }
}

// C(half-row) = a(full row) @ B^T (B rows in smem, stride 20)
__device__ __forceinline__ void wmm16t(const float a[16], const float* Bs, int c0, float c[8]) {
    #pragma unroll
    for (int i = 0; i < 8; i++) {
        const float* br = Bs + (c0 + i) * 20;
        float4 b0 = *(const float4*)(br);
        float4 b1 = *(const float4*)(br + 4);
        float4 b2 = *(const float4*)(br + 8);
        float4 b3 = *(const float4*)(br + 12);
        c[i] = a[0]*b0.x + a[1]*b0.y + a[2]*b0.z + a[3]*b0.w
             + a[4]*b1.x + a[5]*b1.y + a[6]*b1.z + a[7]*b1.w
             + a[8]*b2.x + a[9]*b2.y + a[10]*b2.z + a[11]*b2.w
             + a[12]*b3.x + a[13]*b3.y + a[14]*b3.z + a[15]*b3.w;
    }
}

__device__ __forceinline__ void stoh(float* Bs, int r, int c0, const float h[8]) {
    *(float4*)(Bs + r * 20 + c0)     = make_float4(h[0], h[1], h[2], h[3]);
    *(float4*)(Bs + r * 20 + c0 + 4) = make_float4(h[4], h[5], h[6], h[7]);
}

// =====================================================================
// Kernel 0: one-block precompute of batch-invariant matrices (proven)
// =====================================================================
__global__ void precompute_kernel(const float* __restrict__ ref_params,
                                  const float* __restrict__ bias_spd,
                                  const float* __restrict__ bias_gr)
{
    __shared__ float Bs[256], E[256];
    __shared__ float A20[400];
    __shared__ float Aug[20][40];
    __shared__ float prow[40], fcol[20];
    __shared__ float pv;

    const int tid = threadIdx.x;
    const int i = tid >> 4, j = tid & 15;

    // ---- rel = prod of 120 Givens rotations, each lane owns one row ----
    if (tid < 16) {
        float row[16];
        #pragma unroll
        for (int c = 0; c < 16; c++) row[c] = (c == tid) ? 1.f : 0.f;
        int m = 0;
        for (int pi = 0; pi < 16; pi++) {
            for (int pj = pi + 1; pj < 16; pj++) {
                float ang = ref_params[m++];
                float c = cosf(ang), s = sinf(ang);
                float a = row[pi], b = row[pj];
                row[pi] = c * a + s * b;
                row[pj] = -s * a + c * b;
            }
        }
        #pragma unroll
        for (int c = 0; c < 16; c++) g_rel[tid * 16 + c] = row[c];
    }

    // ---- W = expm(-0.25*(bias+bias^T)) via scaling(2^-7) + Taylor-8 ----
    {
        float v = -0.25f * (bias_spd[i * 16 + j] + bias_spd[j * 16 + i]);
        Bs[tid] = v * (1.0f / 128.0f);
        E[tid]  = (i == j) ? 1.f : 0.f;
    }
    __syncthreads();
    for (int k = 8; k >= 1; k--) {
        float a = 0.f;
        #pragma unroll
        for (int kk = 0; kk < 16; kk++) a += Bs[i * 16 + kk] * E[kk * 16 + j];
        __syncthreads();
        E[tid] = ((i == j) ? 1.f : 0.f) + a * (1.0f / (float)k);
        __syncthreads();
    }
    for (int q = 0; q < 7; q++) {
        float a = 0.f;
        #pragma unroll
        for (int kk = 0; kk < 16; kk++) a += E[i * 16 + kk] * E[kk * 16 + j];
        __syncthreads();
        E[tid] = a;
        __syncthreads();
    }
    g_W[tid] = E[tid];

    // ---- Ybg = (I - A)(I + A)^{-1}, A = skew(bias_gr) 20x20 ----
    for (int e = tid; e < 400; e += 256) {
        int ii = e / 20, jj = e % 20;
        float v = 0.f;
        if (ii < 10 && jj >= 10)      v =  bias_gr[ii * 10 + (jj - 10)];
        else if (ii >= 10 && jj < 10) v = -bias_gr[jj * 10 + (ii - 10)];
        A20[e] = v;
    }
    __syncthreads();
    for (int e = tid; e < 800; e += 256) {
        int ii = e / 40, jj = e % 40;
        float v;
        if (jj < 20) v = ((ii == jj) ? 1.f : 0.f) + A20[ii * 20 + jj];
        else         v = ((jj - 20) == ii) ? 1.f : 0.f;
        Aug[ii][jj] = v;
    }
    __syncthreads();
    for (int p = 0; p < 20; p++) {
        if (tid == 0) pv = Aug[p][p];
        __syncthreads();
        if (tid < 40) prow[tid] = Aug[p][tid] / pv;
        if (tid >= 64 && tid < 84) {
            int r = tid - 64;
            fcol[r] = (r == p) ? 0.f : Aug[r][p];
        }
        __syncthreads();
        for (int e = tid; e < 800; e += 256) {
            int ii = e / 40, jj = e % 40;
            Aug[ii][jj] = (ii == p) ? prow[jj] : Aug[ii][jj] - fcol[ii] * prow[jj];
        }
        __syncthreads();
    }
    for (int e = tid; e < 400; e += 256) {
        int ii = e / 20, jj = e % 20;
        float a = 0.f;
        #pragma unroll
        for (int k = 0; k < 20; k++) {
            float l = ((ii == k) ? 1.f : 0.f) - A20[ii * 20 + k];
            a += l * Aug[k][jj + 20];
        }
        g_Ybg[e] = a;
    }
}

// =====================================================================
// Kernel 1: SPD chains, 1 warp per (b, table).
//   intermediate tokens: Sm = I + A  (Taylor-1, ||A||~3e-3)  -> P = P + P@A
//   last token:          Exp = I + A + A^2/2, Y = P @ Exp @ P^T
// =====================================================================
__global__ void __launch_bounds__(256)
spd_chain_kernel(const int* __restrict__ q_ids, const int* __restrict__ a_ids,
                 const float* __restrict__ q_emb, const float* __restrict__ a_emb,
                 int B, int T)
{
    __shared__ float sb[8][640];
    const int w = threadIdx.x >> 5, lane = threadIdx.x & 31;
    const int gw = blockIdx.x * 8 + w;
    if (gw >= 2 * B) return;
    const int table = gw & 1, b = gw >> 1;
    const int* ids = table ? a_ids : q_ids;
    const float* emb = table ? a_emb : q_emb;
    const int r = lane >> 1, cpar = lane & 1, c0 = cpar * 8;
    float* bufA = sb[w];
    float* bufB = sb[w] + 320;

    float P[8];
    #pragma unroll
    for (int i = 0; i < 8; i++) P[i] = ((r >> 3) == cpar && (r & 7) == i) ? 1.f : 0.f;

    #pragma unroll 1
    for (int t = 0; t < T - 1; t++) {
        int id = ids[b * T + t];
        const float* rp = emb + (size_t)id * 256 + r * 16 + c0;
        float4 e0 = *(const float4*)rp;
        float4 e1 = *(const float4*)(rp + 4);
        __syncwarp();                                  // prior-token bufA/bufB reads done
        *(float4*)(bufA + r * 20 + c0)     = e0;
        *(float4*)(bufA + r * 20 + c0 + 4) = e1;
        __syncwarp();                                  // E visible
        float er[8] = {e0.x, e0.y, e0.z, e0.w, e1.x, e1.y, e1.z, e1.w};
        float Ah[8];
        #pragma unroll
        for (int i = 0; i < 8; i++) Ah[i] = 0.25f * (er[i] + bufA[(c0 + i) * 20 + r]);
        stoh(bufB, r, c0, Ah);
        __syncwarp();                                  // A visible
        float p16[16]; fullrow16(P, cpar, p16);
        float PA[8];  wmm16(p16, bufB, c0, PA);        // P @ A
        #pragma unroll
        for (int i = 0; i < 8; i++) P[i] += PA[i];     // P(I + A)
    }

    // ---- last token: full exp, Taylor-2, then P @ Exp @ P^T ----
    {
        int id = ids[b * T + (T - 1)];
        const float* rp = emb + (size_t)id * 256 + r * 16 + c0;
        float4 e0 = *(const float4*)rp;
        float4 e1 = *(const float4*)(rp + 4);
        __syncwarp();
        *(float4*)(bufA + r * 20 + c0)     = e0;
        *(float4*)(bufA + r * 20 + c0 + 4) = e1;
        __syncwarp();
        float er[8] = {e0.x, e0.y, e0.z, e0.w, e1.x, e1.y, e1.z, e1.w};
        float Ah[8];
        #pragma unroll
        for (int i = 0; i < 8; i++) Ah[i] = 0.5f * (er[i] + bufA[(c0 + i) * 20 + r]);
        stoh(bufB, r, c0, Ah);
        __syncwarp();
        float a16[16]; fullrow16(Ah, cpar, a16);
        float A2[8];  wmm16(a16, bufB, c0, A2);
        float Sm[8];
        #pragma unroll
        for (int i = 0; i < 8; i++) Sm[i] = Ah[i] + 0.5f * A2[i];
        if ((r >> 3) == cpar) Sm[r & 7] += 1.f;
        __syncwarp();
        stoh(bufB, r, c0, Sm);
        stoh(bufA, r, c0, P);                          // stash P for transpose
        __syncwarp();
        float p16[16]; fullrow16(P, cpar, p16);
        float Pn[8];  wmm16(p16, bufB, c0, Pn);        // P @ Exp
        float t16[16]; fullrow16(Pn, cpar, t16);
        float Y[8];   wmm16t(t16, bufA, c0, Y);        // @ P^T
        *(float4*)(&g_X[table][b][r * 16 + c0])     = make_float4(Y[0], Y[1], Y[2], Y[3]);
        *(float4*)(&g_X[table][b][r * 16 + c0 + 4]) = make_float4(Y[4], Y[5], Y[6], Y[7]);
    }
}

// =====================================================================
// Kernel 2: Grassmannian, 1 warp per b, both tables (proven in R10).
// =====================================================================
__global__ void __launch_bounds__(256)
gr_chain_kernel(const int* __restrict__ q_ids, const int* __restrict__ a_ids,
                const float* __restrict__ q_emb, const float* __restrict__ a_emb,
                const float* __restrict__ trans, int B, int T)
{
    __shared__ float xs[8][240];
    __shared__ float q1s[8][200];
    __shared__ float YbgT[400];
    __shared__ float transS[100];
    for (int e = threadIdx.x; e < 400; e += blockDim.x) {
        int ii = e / 20, kk = e - ii * 20;
        YbgT[kk * 20 + ii] = g_Ybg[e];
    }
    for (int e = threadIdx.x; e < 100; e += blockDim.x) transS[e] = trans[e];
    __syncthreads();

    const int w = threadIdx.x >> 5, lane = threadIdx.x & 31;
    const int b = blockIdx.x * 8 + w;
    if (b >= B) return;
    float* xw = xs[w];
    const int tbl = lane / 10;
    const int j = lane - tbl * 10;
    const bool active = lane < 20;

    float Mt[10], Mb[10];
    #pragma unroll
    for (int k = 0; k < 10; k++) { Mt[k] = (k == j && active) ? 1.f : 0.f; Mb[k] = 0.f; }

    #pragma unroll 1
    for (int t = T - 1; t >= 0; t--) {
        int qid = q_ids[b * T + t], aid = a_ids[b * T + t];
        __syncwarp();
        for (int e = lane; e < 100; e += 32) {
            int rr = e / 10, cc = e - rr * 10;
            xw[rr * 12 + cc]       = q_emb[(size_t)qid * 100 + e] * transS[e];
            xw[120 + rr * 12 + cc] = a_emb[(size_t)aid * 100 + e];
        }
        __syncwarp();
        if (active) {
            const float* xb = xw + tbl * 120;
            float u[10], v[10], w1[10], w2[10];
            #pragma unroll
            for (int k = 0; k < 10; k++) { v[k] = 0.f; w2[k] = 0.f; }
            #pragma unroll
            for (int k = 0; k < 10; k++) {
                float4 r0 = *(const float4*)(xb + k * 12);
                float4 r1 = *(const float4*)(xb + k * 12 + 4);
                float4 r2 = *(const float4*)(xb + k * 12 + 8);
                float xr[10] = {r0.x,r0.y,r0.z,r0.w, r1.x,r1.y,r1.z,r1.w, r2.x,r2.y};
                float s = 0.f;
                #pragma unroll
                for (int c = 0; c < 10; c++) s += xr[c] * Mb[c];
                u[k] = s;
                float mtk = Mt[k];
                #pragma unroll
                for (int c = 0; c < 10; c++) v[c] += mtk * xr[c];
            }
            #pragma unroll
            for (int k = 0; k < 10; k++) {
                float4 r0 = *(const float4*)(xb + k * 12);
                float4 r1 = *(const float4*)(xb + k * 12 + 4);
                float4 r2 = *(const float4*)(xb + k * 12 + 8);
                float xr[10] = {r0.x,r0.y,r0.z,r0.w, r1.x,r1.y,r1.z,r1.w, r2.x,r2.y};
                float s = 0.f;
                #pragma unroll
                for (int c = 0; c < 10; c++) s += xr[c] * v[c];
                w1[k] = s;
                float uk = u[k];
                #pragma unroll
                for (int c = 0; c < 10; c++) w2[c] += uk * xr[c];
            }
            #pragma unroll
            for (int k = 0; k < 10; k++) {
                Mt[k] = Mt[k] - 2.f * u[k] - 2.f * w1[k];
                Mb[k] = Mb[k] + 2.f * v[k] - 2.f * w2[k];
            }
        }
    }

    // ---- epilogue ----
    float* q1w = q1s[w];
    if (lane < 10) {
        float Q1[20];
        #pragma unroll
        for (int i = 0; i < 20; i++) Q1[i] = 0.f;
        #pragma unroll
        for (int k = 0; k < 20; k++) {
            float ck = (k < 10) ? Mt[k] : Mb[k - 10];
            const float* yr = YbgT + k * 20;
            float4 y0 = *(const float4*)yr,       y1 = *(const float4*)(yr + 4),
                   y2 = *(const float4*)(yr + 8), y3 = *(const float4*)(yr + 12),
                   y4 = *(const float4*)(yr + 16);
            Q1[0]+=ck*y0.x; Q1[1]+=ck*y0.y; Q1[2]+=ck*y0.z; Q1[3]+=ck*y0.w;
            Q1[4]+=ck*y1.x; Q1[5]+=ck*y1.y; Q1[6]+=ck*y1.z; Q1[7]+=ck*y1.w;
            Q1[8]+=ck*y2.x; Q1[9]+=ck*y2.y; Q1[10]+=ck*y2.z; Q1[11]+=ck*y2.w;
            Q1[12]+=ck*y3.x; Q1[13]+=ck*y3.y; Q1[14]+=ck*y3.z; Q1[15]+=ck*y3.w;
            Q1[16]+=ck*y4.x; Q1[17]+=ck*y4.y; Q1[18]+=ck*y4.z; Q1[19]+=ck*y4.w;
        }
        #pragma unroll
        for (int i = 0; i < 20; i += 4)
            *(float4*)(q1w + j * 20 + i) = make_float4(Q1[i], Q1[i+1], Q1[i+2], Q1[i+3]);
    }
    __syncwarp();
    float s_loc = 0.f;
    if (lane >= 10 && lane < 20) {
        #pragma unroll
        for (int i = 0; i < 10; i++) {
            const float* qc = q1w + i * 20;
            float4 a0 = *(const float4*)qc,       a1 = *(const float4*)(qc + 4),
                   a2 = *(const float4*)(qc + 8), a3 = *(const float4*)(qc + 12),
                   a4 = *(const float4*)(qc + 16);
            float qv[20] = {a0.x,a0.y,a0.z,a0.w, a1.x,a1.y,a1.z,a1.w,
                            a2.x,a2.y,a2.z,a2.w, a3.x,a3.y,a3.z,a3.w,
                            a4.x,a4.y,a4.z,a4.w};
            float d = 0.f;
            #pragma unroll
            for (int k = 0; k < 20; k++) d += qv[k] * ((k < 10) ? Mt[k] : Mb[k - 10]);
            s_loc += d * d;
        }
    }
    #pragma unroll
    for (int o = 16; o; o >>= 1) s_loc += __shfl_xor_sync(0xffffffffu, s_loc, o);
    if (lane == 0) g_dgr[b] = sqrtf(fmaxf(20.f - 2.f * s_loc, 0.f));
}

// =====================================================================
// Kernel 3: finalize, 1 warp per b. rel-conj, Newton-Schulz X^{-1/2},
// m = W (Z Xa Z) W, one-pass warp Jacobi eigenvalues, combine with g_dgr.
// =====================================================================
__global__ void __launch_bounds__(256)
finalize_kernel(float* __restrict__ out, const float* __restrict__ wf,
                const float* __restrict__ wb, int B)
{
    __shared__ float sb[8][640];
    __shared__ float RelS[320], WS[320];
    __shared__ int   partS[8][16];
    for (int e = threadIdx.x; e < 256; e += blockDim.x) {
        RelS[(e >> 4) * 20 + (e & 15)] = g_rel[e];
        WS  [(e >> 4) * 20 + (e & 15)] = g_W[e];
    }
    __syncthreads();
    const int w = threadIdx.x >> 5, lane = threadIdx.x & 31;
    const int b = blockIdx.x * 8 + w;
    if (b >= B) return;
    const int r = lane >> 1, cpar = lane & 1, c0 = cpar * 8;
    float* bufA = sb[w];
    float* bufB = sb[w] + 320;

    // ---- X = Rel @ Xq @ Rel^T ----
    {
        float4 x0 = *(const float4*)(&g_X[0][b][r * 16 + c0]);
        float4 x1 = *(const float4*)(&g_X[0][b][r * 16 + c0 + 4]);
        float h[8] = {x0.x,x0.y,x0.z,x0.w, x1.x,x1.y,x1.z,x1.w};
        stoh(bufA, r, c0, h);
    }
    __syncwarp();
    float Y[8], Z[8];
    {
        const float* rr = RelS + r * 20;
        float4 r0 = *(const float4*)rr,       r1 = *(const float4*)(rr + 4),
               r2 = *(const float4*)(rr + 8), r3 = *(const float4*)(rr + 12);
        float a16[16] = {r0.x,r0.y,r0.z,r0.w, r1.x,r1.y,r1.z,r1.w,
                         r2.x,r2.y,r2.z,r2.w, r3.x,r3.y,r3.z,r3.w};
        float T1[8]; wmm16(a16, bufA, c0, T1);
        float t16[16]; fullrow16(T1, cpar, t16);
        wmm16t(t16, RelS, c0, Y);
    }
    #pragma unroll
    for (int i = 0; i < 8; i++) Z[i] = ((r >> 3) == cpar && (r & 7) == i) ? 1.f : 0.f;

    // ---- Newton-Schulz: Z -> X^{-1/2} ----
    #pragma unroll 1
    for (int it = 0; it < NS_ITERS; it++) {
        __syncwarp(); stoh(bufA, r, c0, Y); __syncwarp();
        float z16[16]; fullrow16(Z, cpar, z16);
        float G[8];   wmm16(z16, bufA, c0, G);          // Z@Y
        #pragma unroll
        for (int i = 0; i < 8; i++) G[i] = -0.5f * G[i];
        if ((r >> 3) == cpar) G[r & 7] += 1.5f;
        __syncwarp(); stoh(bufB, r, c0, G); __syncwarp();
        float y16[16]; fullrow16(Y, cpar, y16);
        float Yn[8];  wmm16(y16, bufB, c0, Yn);         // Y@G
        __syncwarp(); stoh(bufA, r, c0, Z); __syncwarp();
        float g16[16]; fullrow16(G, cpar, g16);
        float Zn[8];  wmm16(g16, bufA, c0, Zn);         // G@Z
        #pragma unroll
        for (int i = 0; i < 8; i++) { Y[i] = Yn[i]; Z[i] = Zn[i]; }
    }

    // ---- m = W @ (Z @ Xa @ Z) @ W ----
    {
        float4 x0 = *(const float4*)(&g_X[1][b][r * 16 + c0]);
        float4 x1 = *(const float4*)(&g_X[1][b][r * 16 + c0 + 4]);
        float xa[8] = {x0.x,x0.y,x0.z,x0.w, x1.x,x1.y,x1.z,x1.w};
        __syncwarp(); stoh(bufA, r, c0, xa); __syncwarp();
    }
    {
        float z16[16]; fullrow16(Z, cpar, z16);
        float U[8];  wmm16(z16, bufA, c0, U);           // Z@Xa
        __syncwarp(); stoh(bufA, r, c0, Z); __syncwarp();
        float u16[16]; fullrow16(U, cpar, u16);
        float K[8];  wmm16(u16, bufA, c0, K);           // (Z Xa) Z
        __syncwarp(); stoh(bufA, r, c0, K); __syncwarp();
        const float* wr = WS + r * 20;
        float4 w0 = *(const float4*)wr,       w1 = *(const float4*)(wr + 4),
               w2 = *(const float4*)(wr + 8), w3 = *(const float4*)(wr + 12);
        float wrow[16] = {w0.x,w0.y,w0.z,w0.w, w1.x,w1.y,w1.z,w1.w,
                          w2.x,w2.y,w2.z,w2.w, w3.x,w3.y,w3.z,w3.w};
        float V[8]; wmm16(wrow, bufA, c0, V);           // W@K
        float v16[16]; fullrow16(V, cpar, v16);
        float Mh[8]; wmm16(v16, WS, c0, Mh);            // (W K) W
        __syncwarp(); stoh(bufA, r, c0, Mh); __syncwarp();
    }

    // ---- one-pass warp Jacobi eigenvalues ----
    float* cjs = bufB;          // [16]
    float* bjs = bufB + 16;     // [16]
    int*   pp  = partS[w];
    #pragma unroll 1
    for (int sweep = 0; sweep < JAC_SWEEPS; sweep++) {
        #pragma unroll 1
        for (int rr = 0; rr < 15; rr++) {
            if (lane < 8) {
                int pI, qI;
                if (lane == 0) { pI = 0; qI = 1 + ((14 + rr) % 15); }
                else { pI = 1 + ((lane - 1 + rr) % 15); qI = 1 + ((14 - lane + rr) % 15); }
                float app = bufA[pI * 20 + pI], aqq = bufA[qI * 20 + qI], apq = bufA[pI * 20 + qI];
                float cc_, ss_;
                if (fabsf(apq) < 1e-30f) { cc_ = 1.f; ss_ = 0.f; }
                else {
                    float tau = (aqq - app) / (2.f * apq);
                    float tt = (tau >= 0.f ? 1.f : -1.f) / (fabsf(tau) + sqrtf(1.f + tau * tau));
                    cc_ = rsqrtf(1.f + tt * tt); ss_ = tt * cc_;
                }
                pp[pI] = qI; pp[qI] = pI;
                cjs[pI] = cc_; cjs[qI] = cc_; bjs[pI] = -ss_; bjs[qI] = ss_;
            }
            __syncwarp();
            // gather
            float cr = cjs[r], br = bjs[r];
            int pr = pp[r];
            float4 cv0 = *(const float4*)(cjs + c0), cv1 = *(const float4*)(cjs + c0 + 4);
            float4 bv0 = *(const float4*)(bjs + c0), bv1 = *(const float4*)(bjs + c0 + 4);
            float ccA[8] = {cv0.x,cv0.y,cv0.z,cv0.w, cv1.x,cv1.y,cv1.z,cv1.w};
            float bbA[8] = {bv0.x,bv0.y,bv0.z,bv0.w, bv1.x,bv1.y,bv1.z,bv1.w};
            float4 a0 = *(const float4*)(bufA + r * 20 + c0);
            float4 a1 = *(const float4*)(bufA + r * 20 + c0 + 4);
            float4 p0 = *(const float4*)(bufA + pr * 20 + c0);
            float4 p1 = *(const float4*)(bufA + pr * 20 + c0 + 4);
            float arc[8]  = {a0.x,a0.y,a0.z,a0.w, a1.x,a1.y,a1.z,a1.w};
            float aprc[8] = {p0.x,p0.y,p0.z,p0.w, p1.x,p1.y,p1.z,p1.w};
            float arpc[8], aprpc[8];
            #pragma unroll
            for (int i = 0; i < 8; i++) {
                int pc = pp[c0 + i];
                arpc[i]  = bufA[r * 20 + pc];
                aprpc[i] = bufA[pr * 20 + pc];
            }
            __syncwarp();
            // update: A' = J^T A J, fused
            float nv[8];
            #pragma unroll
            for (int i = 0; i < 8; i++)
                nv[i] = cr * (ccA[i] * arc[i] + bbA[i] * arpc[i])
                      + br * (ccA[i] * aprc[i] + bbA[i] * aprpc[i]);
            stoh(bufA, r, c0, nv);
            __syncwarp();
        }
    }

    float acc = 0.f;
    if (lane < 16) {
        float d = bufA[lane * 20 + lane];
        float l = logf(fmaxf(d, 1e-30f));
        acc = l * l;
    }
    #pragma unroll
    for (int o = 8; o; o >>= 1) acc += __shfl_xor_sync(0xffffffffu, acc, o);
    if (lane == 0) out[b] = -wf[0] * (sqrtf(acc) + g_dgr[b]) + wb[0];
}

// =====================================================================
extern "C" void kernel_launch(void* const* d_in, const int* in_sizes, int n_in,
                              void* d_out, int out_size)
{
    const int*   q_ids      = (const int*)  d_in[0];
    const int*   a_ids      = (const int*)  d_in[1];
    const float* q_emb_spd  = (const float*)d_in[2];
    const float* a_emb_spd  = (const float*)d_in[3];
    const float* ref_params = (const float*)d_in[4];
    const float* bias_spd   = (const float*)d_in[5];
    const float* q_emb_gr   = (const float*)d_in[6];
    const float* a_emb_gr   = (const float*)d_in[7];
    const float* trans_gr   = (const float*)d_in[8];
    const float* bias_gr    = (const float*)d_in[9];
    const float* wf         = (const float*)d_in[10];
    const float* wb         = (const float*)d_in[11];
    float* out = (float*)d_out;

    int B = out_size;
    if (B > BMAX) B = BMAX;
    int T = in_sizes[0] / B;

    precompute_kernel<<<1, 256>>>(ref_params, bias_spd, bias_gr);
    spd_chain_kernel<<<(2 * B + 7) / 8, 256>>>(q_ids, a_ids, q_emb_spd, a_emb_spd, B, T);
    gr_chain_kernel<<<(B + 7) / 8, 256>>>(q_ids, a_ids, q_emb_gr, a_emb_gr, trans_gr, B, T);
    finalize_kernel<<<(B + 7) / 8, 256>>>(out, wf, wb, B);
}

// round 12
// speedup vs baseline: 3.2939x; 1.1838x over previous
#include <cuda_runtime.h>
#include <math.h>

#define BMAX 2048
#define NS_ITERS 3
#define JAC_SWEEPS 6

// ---------------- device scratch (no allocations allowed) ----------------
__device__ float g_rel[256];            // 16x16 isometry
__device__ float g_W[256];              // expm(-sym(bias_spd)/2)
__device__ float g_Ybg[400];            // cayley(bias_gr) 20x20
__device__ float g_X[2][BMAX][256];     // SPD chain results (0=q,1=a)
__device__ float g_dgr[BMAX];           // per-batch Grassmannian distance

// =====================================================================
// warp-level 16x16 helpers. Layout: lane = 2*r + cpar, lane owns row r,
// cols c0..c0+7 (c0 = cpar*8). Smem tiles row-major, stride 20 floats.
// =====================================================================
__device__ __forceinline__ void fullrow16(const float h[8], int cpar, float a[16]) {
    #pragma unroll
    for (int i = 0; i < 8; i++) {
        float o = __shfl_xor_sync(0xffffffffu, h[i], 1);
        a[i]     = cpar ? o    : h[i];
        a[8 + i] = cpar ? h[i] : o;
    }
}

// C(half-row) = a(full row) @ B(smem, stride 20)
__device__ __forceinline__ void wmm16(const float a[16], const float* Bs, int c0, float c[8]) {
    #pragma unroll
    for (int i = 0; i < 8; i++) c[i] = 0.f;
    #pragma unroll
    for (int k = 0; k < 16; k++) {
        float4 b0 = *(const float4*)(Bs + k * 20 + c0);
        float4 b1 = *(const float4*)(Bs + k * 20 + c0 + 4);
        float ak = a[k];
        c[0] += ak * b0.x; c[1] += ak * b0.y; c[2] += ak * b0.z; c[3] += ak * b0.w;
        c[4] += ak * b1.x; c[5] += ak * b1.y; c[6] += ak * b1.z; c[7] += ak * b1.w;
    }
}

// C(half-row) = a(full row) @ B^T (B rows in smem, stride 20)
__device__ __forceinline__ void wmm16t(const float a[16], const float* Bs, int c0, float c[8]) {
    #pragma unroll
    for (int i = 0; i < 8; i++) {
        const float* br = Bs + (c0 + i) * 20;
        float4 b0 = *(const float4*)(br);
        float4 b1 = *(const float4*)(br + 4);
        float4 b2 = *(const float4*)(br + 8);
        float4 b3 = *(const float4*)(br + 12);
        c[i] = a[0]*b0.x + a[1]*b0.y + a[2]*b0.z + a[3]*b0.w
             + a[4]*b1.x + a[5]*b1.y + a[6]*b1.z + a[7]*b1.w
             + a[8]*b2.x + a[9]*b2.y + a[10]*b2.z + a[11]*b2.w
             + a[12]*b3.x + a[13]*b3.y + a[14]*b3.z + a[15]*b3.w;
    }
}

__device__ __forceinline__ void stoh(float* Bs, int r, int c0, const float h[8]) {
    *(float4*)(Bs + r * 20 + c0)     = make_float4(h[0], h[1], h[2], h[3]);
    *(float4*)(Bs + r * 20 + c0 + 4) = make_float4(h[4], h[5], h[6], h[7]);
}

// =====================================================================
// Kernel 0: one-block precompute of batch-invariant matrices (proven)
// =====================================================================
__global__ void precompute_kernel(const float* __restrict__ ref_params,
                                  const float* __restrict__ bias_spd,
                                  const float* __restrict__ bias_gr)
{
    __shared__ float Bs[256], E[256];
    __shared__ float A20[400];
    __shared__ float Aug[20][40];
    __shared__ float prow[40], fcol[20];
    __shared__ float pv;

    const int tid = threadIdx.x;
    const int i = tid >> 4, j = tid & 15;

    // ---- rel = prod of 120 Givens rotations, each lane owns one row ----
    if (tid < 16) {
        float row[16];
        #pragma unroll
        for (int c = 0; c < 16; c++) row[c] = (c == tid) ? 1.f : 0.f;
        int m = 0;
        for (int pi = 0; pi < 16; pi++) {
            for (int pj = pi + 1; pj < 16; pj++) {
                float ang = ref_params[m++];
                float c = cosf(ang), s = sinf(ang);
                float a = row[pi], b = row[pj];
                row[pi] = c * a + s * b;
                row[pj] = -s * a + c * b;
            }
        }
        #pragma unroll
        for (int c = 0; c < 16; c++) g_rel[tid * 16 + c] = row[c];
    }

    // ---- W = expm(-0.25*(bias+bias^T)) via scaling(2^-7) + Taylor-8 ----
    {
        float v = -0.25f * (bias_spd[i * 16 + j] + bias_spd[j * 16 + i]);
        Bs[tid] = v * (1.0f / 128.0f);
        E[tid]  = (i == j) ? 1.f : 0.f;
    }
    __syncthreads();
    for (int k = 8; k >= 1; k--) {
        float a = 0.f;
        #pragma unroll
        for (int kk = 0; kk < 16; kk++) a += Bs[i * 16 + kk] * E[kk * 16 + j];
        __syncthreads();
        E[tid] = ((i == j) ? 1.f : 0.f) + a * (1.0f / (float)k);
        __syncthreads();
    }
    for (int q = 0; q < 7; q++) {
        float a = 0.f;
        #pragma unroll
        for (int kk = 0; kk < 16; kk++) a += E[i * 16 + kk] * E[kk * 16 + j];
        __syncthreads();
        E[tid] = a;
        __syncthreads();
    }
    g_W[tid] = E[tid];

    // ---- Ybg = (I - A)(I + A)^{-1}, A = skew(bias_gr) 20x20 ----
    for (int e = tid; e < 400; e += 256) {
        int ii = e / 20, jj = e % 20;
        float v = 0.f;
        if (ii < 10 && jj >= 10)      v =  bias_gr[ii * 10 + (jj - 10)];
        else if (ii >= 10 && jj < 10) v = -bias_gr[jj * 10 + (ii - 10)];
        A20[e] = v;
    }
    __syncthreads();
    for (int e = tid; e < 800; e += 256) {
        int ii = e / 40, jj = e % 40;
        float v;
        if (jj < 20) v = ((ii == jj) ? 1.f : 0.f) + A20[ii * 20 + jj];
        else         v = ((jj - 20) == ii) ? 1.f : 0.f;
        Aug[ii][jj] = v;
    }
    __syncthreads();
    for (int p = 0; p < 20; p++) {
        if (tid == 0) pv = Aug[p][p];
        __syncthreads();
        if (tid < 40) prow[tid] = Aug[p][tid] / pv;
        if (tid >= 64 && tid < 84) {
            int r = tid - 64;
            fcol[r] = (r == p) ? 0.f : Aug[r][p];
        }
        __syncthreads();
        for (int e = tid; e < 800; e += 256) {
            int ii = e / 40, jj = e % 40;
            Aug[ii][jj] = (ii == p) ? prow[jj] : Aug[ii][jj] - fcol[ii] * prow[jj];
        }
        __syncthreads();
    }
    for (int e = tid; e < 400; e += 256) {
        int ii = e / 20, jj = e % 20;
        float a = 0.f;
        #pragma unroll
        for (int k = 0; k < 20; k++) {
            float l = ((ii == k) ? 1.f : 0.f) - A20[ii * 20 + k];
            a += l * Aug[k][jj + 20];
        }
        g_Ybg[e] = a;
    }
}

// =====================================================================
// Kernel 1: SPD chains, 1 warp per (b, table). Tokens 0..T-2 applied in
// PAIRS: P <- P(I + A_t + A_{t+1})  (cross term ~8e-6, dropped).
// Last token: Exp = I + A + A^2/2, Y = P @ Exp @ P^T.
// =====================================================================
__global__ void __launch_bounds__(256)
spd_chain_kernel(const int* __restrict__ q_ids, const int* __restrict__ a_ids,
                 const float* __restrict__ q_emb, const float* __restrict__ a_emb,
                 int B, int T)
{
    __shared__ float sb[8][640];
    const int w = threadIdx.x >> 5, lane = threadIdx.x & 31;
    const int gw = blockIdx.x * 8 + w;
    if (gw >= 2 * B) return;
    const int table = gw & 1, b = gw >> 1;
    const int* ids = table ? a_ids : q_ids;
    const float* emb = table ? a_emb : q_emb;
    const int r = lane >> 1, cpar = lane & 1, c0 = cpar * 8;
    float* bufA = sb[w];
    float* bufB = sb[w] + 320;

    float P[8];
    #pragma unroll
    for (int i = 0; i < 8; i++) P[i] = ((r >> 3) == cpar && (r & 7) == i) ? 1.f : 0.f;

    const int nmid = T - 1;
    #pragma unroll 1
    for (int t = 0; t < nmid; t += 2) {
        float er[8];
        {
            int id0 = ids[b * T + t];
            const float* rp = emb + (size_t)id0 * 256 + r * 16 + c0;
            float4 e0 = *(const float4*)rp;
            float4 e1 = *(const float4*)(rp + 4);
            er[0]=e0.x; er[1]=e0.y; er[2]=e0.z; er[3]=e0.w;
            er[4]=e1.x; er[5]=e1.y; er[6]=e1.z; er[7]=e1.w;
        }
        if (t + 1 < nmid) {
            int id1 = ids[b * T + t + 1];
            const float* rp = emb + (size_t)id1 * 256 + r * 16 + c0;
            float4 e0 = *(const float4*)rp;
            float4 e1 = *(const float4*)(rp + 4);
            er[0]+=e0.x; er[1]+=e0.y; er[2]+=e0.z; er[3]+=e0.w;
            er[4]+=e1.x; er[5]+=e1.y; er[6]+=e1.z; er[7]+=e1.w;
        }
        __syncwarp();                                  // prior-iter buf reads done
        stoh(bufA, r, c0, er);
        __syncwarp();                                  // Esum visible
        float Ah[8];
        #pragma unroll
        for (int i = 0; i < 8; i++) Ah[i] = 0.25f * (er[i] + bufA[(c0 + i) * 20 + r]);
        stoh(bufB, r, c0, Ah);
        __syncwarp();                                  // A visible
        float p16[16]; fullrow16(P, cpar, p16);
        float PA[8];  wmm16(p16, bufB, c0, PA);        // P @ (A_t + A_{t+1})
        #pragma unroll
        for (int i = 0; i < 8; i++) P[i] += PA[i];
    }

    // ---- last token: full exp, Taylor-2, then P @ Exp @ P^T ----
    {
        int id = ids[b * T + (T - 1)];
        const float* rp = emb + (size_t)id * 256 + r * 16 + c0;
        float4 e0 = *(const float4*)rp;
        float4 e1 = *(const float4*)(rp + 4);
        __syncwarp();
        *(float4*)(bufA + r * 20 + c0)     = e0;
        *(float4*)(bufA + r * 20 + c0 + 4) = e1;
        __syncwarp();
        float er[8] = {e0.x, e0.y, e0.z, e0.w, e1.x, e1.y, e1.z, e1.w};
        float Ah[8];
        #pragma unroll
        for (int i = 0; i < 8; i++) Ah[i] = 0.5f * (er[i] + bufA[(c0 + i) * 20 + r]);
        stoh(bufB, r, c0, Ah);
        __syncwarp();
        float a16[16]; fullrow16(Ah, cpar, a16);
        float A2[8];  wmm16(a16, bufB, c0, A2);
        float Sm[8];
        #pragma unroll
        for (int i = 0; i < 8; i++) Sm[i] = Ah[i] + 0.5f * A2[i];
        if ((r >> 3) == cpar) Sm[r & 7] += 1.f;
        __syncwarp();
        stoh(bufB, r, c0, Sm);
        stoh(bufA, r, c0, P);                          // stash P for transpose
        __syncwarp();
        float p16[16]; fullrow16(P, cpar, p16);
        float Pn[8];  wmm16(p16, bufB, c0, Pn);        // P @ Exp
        float t16[16]; fullrow16(Pn, cpar, t16);
        float Y[8];   wmm16t(t16, bufA, c0, Y);        // @ P^T
        *(float4*)(&g_X[table][b][r * 16 + c0])     = make_float4(Y[0], Y[1], Y[2], Y[3]);
        *(float4*)(&g_X[table][b][r * 16 + c0 + 4]) = make_float4(Y[4], Y[5], Y[6], Y[7]);
    }
}

// =====================================================================
// Kernel 2: Grassmannian, 1 warp per b, both tables (proven in R10/R11).
// =====================================================================
__global__ void __launch_bounds__(256)
gr_chain_kernel(const int* __restrict__ q_ids, const int* __restrict__ a_ids,
                const float* __restrict__ q_emb, const float* __restrict__ a_emb,
                const float* __restrict__ trans, int B, int T)
{
    __shared__ float xs[8][240];
    __shared__ float q1s[8][200];
    __shared__ float YbgT[400];
    __shared__ float transS[100];
    for (int e = threadIdx.x; e < 400; e += blockDim.x) {
        int ii = e / 20, kk = e - ii * 20;
        YbgT[kk * 20 + ii] = g_Ybg[e];
    }
    for (int e = threadIdx.x; e < 100; e += blockDim.x) transS[e] = trans[e];
    __syncthreads();

    const int w = threadIdx.x >> 5, lane = threadIdx.x & 31;
    const int b = blockIdx.x * 8 + w;
    if (b >= B) return;
    float* xw = xs[w];
    const int tbl = lane / 10;
    const int j = lane - tbl * 10;
    const bool active = lane < 20;

    float Mt[10], Mb[10];
    #pragma unroll
    for (int k = 0; k < 10; k++) { Mt[k] = (k == j && active) ? 1.f : 0.f; Mb[k] = 0.f; }

    #pragma unroll 1
    for (int t = T - 1; t >= 0; t--) {
        int qid = q_ids[b * T + t], aid = a_ids[b * T + t];
        __syncwarp();
        for (int e = lane; e < 100; e += 32) {
            int rr = e / 10, cc = e - rr * 10;
            xw[rr * 12 + cc]       = q_emb[(size_t)qid * 100 + e] * transS[e];
            xw[120 + rr * 12 + cc] = a_emb[(size_t)aid * 100 + e];
        }
        __syncwarp();
        if (active) {
            const float* xb = xw + tbl * 120;
            float u[10], v[10], w1[10], w2[10];
            #pragma unroll
            for (int k = 0; k < 10; k++) { v[k] = 0.f; w2[k] = 0.f; }
            #pragma unroll
            for (int k = 0; k < 10; k++) {
                float4 r0 = *(const float4*)(xb + k * 12);
                float4 r1 = *(const float4*)(xb + k * 12 + 4);
                float4 r2 = *(const float4*)(xb + k * 12 + 8);
                float xr[10] = {r0.x,r0.y,r0.z,r0.w, r1.x,r1.y,r1.z,r1.w, r2.x,r2.y};
                float s = 0.f;
                #pragma unroll
                for (int c = 0; c < 10; c++) s += xr[c] * Mb[c];
                u[k] = s;
                float mtk = Mt[k];
                #pragma unroll
                for (int c = 0; c < 10; c++) v[c] += mtk * xr[c];
            }
            #pragma unroll
            for (int k = 0; k < 10; k++) {
                float4 r0 = *(const float4*)(xb + k * 12);
                float4 r1 = *(const float4*)(xb + k * 12 + 4);
                float4 r2 = *(const float4*)(xb + k * 12 + 8);
                float xr[10] = {r0.x,r0.y,r0.z,r0.w, r1.x,r1.y,r1.z,r1.w, r2.x,r2.y};
                float s = 0.f;
                #pragma unroll
                for (int c = 0; c < 10; c++) s += xr[c] * v[c];
                w1[k] = s;
                float uk = u[k];
                #pragma unroll
                for (int c = 0; c < 10; c++) w2[c] += uk * xr[c];
            }
            #pragma unroll
            for (int k = 0; k < 10; k++) {
                Mt[k] = Mt[k] - 2.f * u[k] - 2.f * w1[k];
                Mb[k] = Mb[k] + 2.f * v[k] - 2.f * w2[k];
            }
        }
    }

    // ---- epilogue ----
    float* q1w = q1s[w];
    if (lane < 10) {
        float Q1[20];
        #pragma unroll
        for (int i = 0; i < 20; i++) Q1[i] = 0.f;
        #pragma unroll
        for (int k = 0; k < 20; k++) {
            float ck = (k < 10) ? Mt[k] : Mb[k - 10];
            const float* yr = YbgT + k * 20;
            float4 y0 = *(const float4*)yr,       y1 = *(const float4*)(yr + 4),
                   y2 = *(const float4*)(yr + 8), y3 = *(const float4*)(yr + 12),
                   y4 = *(const float4*)(yr + 16);
            Q1[0]+=ck*y0.x; Q1[1]+=ck*y0.y; Q1[2]+=ck*y0.z; Q1[3]+=ck*y0.w;
            Q1[4]+=ck*y1.x; Q1[5]+=ck*y1.y; Q1[6]+=ck*y1.z; Q1[7]+=ck*y1.w;
            Q1[8]+=ck*y2.x; Q1[9]+=ck*y2.y; Q1[10]+=ck*y2.z; Q1[11]+=ck*y2.w;
            Q1[12]+=ck*y3.x; Q1[13]+=ck*y3.y; Q1[14]+=ck*y3.z; Q1[15]+=ck*y3.w;
            Q1[16]+=ck*y4.x; Q1[17]+=ck*y4.y; Q1[18]+=ck*y4.z; Q1[19]+=ck*y4.w;
        }
        #pragma unroll
        for (int i = 0; i < 20; i += 4)
            *(float4*)(q1w + j * 20 + i) = make_float4(Q1[i], Q1[i+1], Q1[i+2], Q1[i+3]);
    }
    __syncwarp();
    float s_loc = 0.f;
    if (lane >= 10 && lane < 20) {
        #pragma unroll
        for (int i = 0; i < 10; i++) {
            const float* qc = q1w + i * 20;
            float4 a0 = *(const float4*)qc,       a1 = *(const float4*)(qc + 4),
                   a2 = *(const float4*)(qc + 8), a3 = *(const float4*)(qc + 12),
                   a4 = *(const float4*)(qc + 16);
            float qv[20] = {a0.x,a0.y,a0.z,a0.w, a1.x,a1.y,a1.z,a1.w,
                            a2.x,a2.y,a2.z,a2.w, a3.x,a3.y,a3.z,a3.w,
                            a4.x,a4.y,a4.z,a4.w};
            float d = 0.f;
            #pragma unroll
            for (int k = 0; k < 20; k++) d += qv[k] * ((k < 10) ? Mt[k] : Mb[k - 10]);
            s_loc += d * d;
        }
    }
    #pragma unroll
    for (int o = 16; o; o >>= 1) s_loc += __shfl_xor_sync(0xffffffffu, s_loc, o);
    if (lane == 0) g_dgr[b] = sqrtf(fmaxf(20.f - 2.f * s_loc, 0.f));
}

// =====================================================================
// Kernel 3: finalize, 1 warp per b. rel-conj, Newton-Schulz X^{-1/2},
// m = W (Z Xa Z) W, then SHFL-RESIDENT Jacobi (rows in registers,
// rounds fully unrolled so column permutation is static; zero smem,
// zero syncwarp). Combine with g_dgr.
// =====================================================================
__global__ void __launch_bounds__(256)
finalize_kernel(float* __restrict__ out, const float* __restrict__ wf,
                const float* __restrict__ wb, int B)
{
    __shared__ float sb[8][640];
    __shared__ float RelS[320], WS[320];
    for (int e = threadIdx.x; e < 256; e += blockDim.x) {
        RelS[(e >> 4) * 20 + (e & 15)] = g_rel[e];
        WS  [(e >> 4) * 20 + (e & 15)] = g_W[e];
    }
    __syncthreads();
    const int w = threadIdx.x >> 5, lane = threadIdx.x & 31;
    const int b = blockIdx.x * 8 + w;
    if (b >= B) return;
    const int r = lane >> 1, cpar = lane & 1, c0 = cpar * 8;
    float* bufA = sb[w];
    float* bufB = sb[w] + 320;

    // ---- X = Rel @ Xq @ Rel^T ----
    {
        float4 x0 = *(const float4*)(&g_X[0][b][r * 16 + c0]);
        float4 x1 = *(const float4*)(&g_X[0][b][r * 16 + c0 + 4]);
        float h[8] = {x0.x,x0.y,x0.z,x0.w, x1.x,x1.y,x1.z,x1.w};
        stoh(bufA, r, c0, h);
    }
    __syncwarp();
    float Y[8], Z[8];
    {
        const float* rr = RelS + r * 20;
        float4 r0 = *(const float4*)rr,       r1 = *(const float4*)(rr + 4),
               r2 = *(const float4*)(rr + 8), r3 = *(const float4*)(rr + 12);
        float a16[16] = {r0.x,r0.y,r0.z,r0.w, r1.x,r1.y,r1.z,r1.w,
                         r2.x,r2.y,r2.z,r2.w, r3.x,r3.y,r3.z,r3.w};
        float T1[8]; wmm16(a16, bufA, c0, T1);
        float t16[16]; fullrow16(T1, cpar, t16);
        wmm16t(t16, RelS, c0, Y);
    }
    #pragma unroll
    for (int i = 0; i < 8; i++) Z[i] = ((r >> 3) == cpar && (r & 7) == i) ? 1.f : 0.f;

    // ---- Newton-Schulz: Z -> X^{-1/2} ----
    #pragma unroll 1
    for (int it = 0; it < NS_ITERS; it++) {
        __syncwarp(); stoh(bufA, r, c0, Y); __syncwarp();
        float z16[16]; fullrow16(Z, cpar, z16);
        float G[8];   wmm16(z16, bufA, c0, G);          // Z@Y
        #pragma unroll
        for (int i = 0; i < 8; i++) G[i] = -0.5f * G[i];
        if ((r >> 3) == cpar) G[r & 7] += 1.5f;
        __syncwarp(); stoh(bufB, r, c0, G); __syncwarp();
        float y16[16]; fullrow16(Y, cpar, y16);
        float Yn[8];  wmm16(y16, bufB, c0, Yn);         // Y@G
        __syncwarp(); stoh(bufA, r, c0, Z); __syncwarp();
        float g16[16]; fullrow16(G, cpar, g16);
        float Zn[8];  wmm16(g16, bufA, c0, Zn);         // G@Z
        #pragma unroll
        for (int i = 0; i < 8; i++) { Y[i] = Yn[i]; Z[i] = Zn[i]; }
    }

    // ---- m = W @ (Z @ Xa @ Z) @ W  (into bufA) ----
    {
        float4 x0 = *(const float4*)(&g_X[1][b][r * 16 + c0]);
        float4 x1 = *(const float4*)(&g_X[1][b][r * 16 + c0 + 4]);
        float xa[8] = {x0.x,x0.y,x0.z,x0.w, x1.x,x1.y,x1.z,x1.w};
        __syncwarp(); stoh(bufA, r, c0, xa); __syncwarp();
    }
    {
        float z16[16]; fullrow16(Z, cpar, z16);
        float U[8];  wmm16(z16, bufA, c0, U);           // Z@Xa
        __syncwarp(); stoh(bufA, r, c0, Z); __syncwarp();
        float u16[16]; fullrow16(U, cpar, u16);
        float K[8];  wmm16(u16, bufA, c0, K);           // (Z Xa) Z
        __syncwarp(); stoh(bufA, r, c0, K); __syncwarp();
        const float* wr = WS + r * 20;
        float4 w0 = *(const float4*)wr,       w1 = *(const float4*)(wr + 4),
               w2 = *(const float4*)(wr + 8), w3 = *(const float4*)(wr + 12);
        float wrow[16] = {w0.x,w0.y,w0.z,w0.w, w1.x,w1.y,w1.z,w1.w,
                          w2.x,w2.y,w2.z,w2.w, w3.x,w3.y,w3.z,w3.w};
        float V[8]; wmm16(wrow, bufA, c0, V);           // W@K
        float v16[16]; fullrow16(V, cpar, v16);
        float Mh[8]; wmm16(v16, WS, c0, Mh);            // (W K) W
        __syncwarp(); stoh(bufA, r, c0, Mh); __syncwarp();
    }

    // ---- shfl-resident Jacobi: lane jr owns row jr (lanes 16-31 mirror) ----
    const int jr = lane & 15;
    float a[16];
    {
        const float* rp = bufA + jr * 20;
        float4 v0 = *(const float4*)rp,        v1 = *(const float4*)(rp + 4),
               v2 = *(const float4*)(rp + 8),  v3 = *(const float4*)(rp + 12);
        a[0]=v0.x; a[1]=v0.y; a[2]=v0.z; a[3]=v0.w;
        a[4]=v1.x; a[5]=v1.y; a[6]=v1.z; a[7]=v1.w;
        a[8]=v2.x; a[9]=v2.y; a[10]=v2.z; a[11]=v2.w;
        a[12]=v3.x; a[13]=v3.y; a[14]=v3.z; a[15]=v3.w;
    }
    #pragma unroll 1
    for (int sweep = 0; sweep < JAC_SWEEPS; sweep++) {
        #pragma unroll
        for (int rr = 0; rr < 15; rr++) {
            // runtime per-lane partner (tournament pairing)
            int u  = (jr == 0) ? 15 : (jr - 1 - rr + 30) % 15;
            int pu = (u == 15) ? 14 : ((u == 14) ? 15 : 13 - u);
            int partner = (pu == 15) ? 0 : 1 + ((pu + rr) % 15);
            bool isp = (jr == 0) || (u <= 6);
            float mydiag = 0.f, across = 0.f;
            #pragma unroll
            for (int i = 0; i < 16; i++) {
                if (i == jr)      mydiag = a[i];
                if (i == partner) across = a[i];
            }
            float partdiag = __shfl_sync(0xffffffffu, mydiag, partner);
            float cc, ss;
            if (fabsf(across) < 1e-30f) { cc = 1.f; ss = 0.f; }
            else {
                float diff = isp ? (partdiag - mydiag) : (mydiag - partdiag);
                float tau = diff / (2.f * across);
                float tt = (tau >= 0.f ? 1.f : -1.f) / (fabsf(tau) + sqrtf(1.f + tau * tau));
                cc = rsqrtf(1.f + tt * tt); ss = tt * cc;
            }
            float bme = isp ? -ss : ss;
            // partner row + row rotation
            float nr[16];
            #pragma unroll
            for (int i = 0; i < 16; i++) {
                float pv = __shfl_sync(0xffffffffu, a[i], partner);
                nr[i] = cc * a[i] + bme * pv;
            }
            // column rotation: static permutation & signs (rr, i compile-time)
            #pragma unroll
            for (int i = 0; i < 16; i++) {
                int ui  = (i == 0) ? 15 : (i - 1 - rr + 30) % 15;
                int pui = (ui == 15) ? 14 : ((ui == 14) ? 15 : 13 - ui);
                int pi_ = (pui == 15) ? 0 : 1 + ((pui + rr) % 15);
                float ciV = __shfl_sync(0xffffffffu, cc, i);
                float siV = __shfl_sync(0xffffffffu, ss, i);
                float biV = ((i == 0) || (ui <= 6)) ? -siV : siV;
                a[i] = ciV * nr[i] + biV * nr[pi_];
            }
        }
    }

    float acc = 0.f;
    if (lane < 16) {
        float d = 0.f;
        #pragma unroll
        for (int i = 0; i < 16; i++) if (i == jr) d = a[i];
        float l = logf(fmaxf(d, 1e-30f));
        acc = l * l;
    }
    #pragma unroll
    for (int o = 8; o; o >>= 1) acc += __shfl_xor_sync(0xffffffffu, acc, o);
    if (lane == 0) out[b] = -wf[0] * (sqrtf(acc) + g_dgr[b]) + wb[0];
}

// =====================================================================
extern "C" void kernel_launch(void* const* d_in, const int* in_sizes, int n_in,
                              void* d_out, int out_size)
{
    const int*   q_ids      = (const int*)  d_in[0];
    const int*   a_ids      = (const int*)  d_in[1];
    const float* q_emb_spd  = (const float*)d_in[2];
    const float* a_emb_spd  = (const float*)d_in[3];
    const float* ref_params = (const float*)d_in[4];
    const float* bias_spd   = (const float*)d_in[5];
    const float* q_emb_gr   = (const float*)d_in[6];
    const float* a_emb_gr   = (const float*)d_in[7];
    const float* trans_gr   = (const float*)d_in[8];
    const float* bias_gr    = (const float*)d_in[9];
    const float* wf         = (const float*)d_in[10];
    const float* wb         = (const float*)d_in[11];
    float* out = (float*)d_out;

    int B = out_size;
    if (B > BMAX) B = BMAX;
    int T = in_sizes[0] / B;

    precompute_kernel<<<1, 256>>>(ref_params, bias_spd, bias_gr);
    spd_chain_kernel<<<(2 * B + 7) / 8, 256>>>(q_ids, a_ids, q_emb_spd, a_emb_spd, B, T);
    gr_chain_kernel<<<(B + 7) / 8, 256>>>(q_ids, a_ids, q_emb_gr, a_emb_gr, trans_gr, B, T);
    finalize_kernel<<<(B + 7) / 8, 256>>>(out, wf, wb, B);
}

// round 13
// speedup vs baseline: 3.8734x; 1.1759x over previous
#include <cuda_runtime.h>
#include <math.h>

#define NS_ITERS 3
#define JAC_SWEEPS 4

// ---------------- device scratch (no allocations allowed) ----------------
__device__ float g_rel[256];            // 16x16 isometry
__device__ float g_W[256];              // expm(-sym(bias_spd)/2)
__device__ float g_Ybg[400];            // cayley(bias_gr) 20x20

// =====================================================================
// warp-level 16x16 helpers. Layout: lane = 2*r + cpar, lane owns row r,
// cols c0..c0+7 (c0 = cpar*8). Smem tiles row-major, stride 20 floats.
// =====================================================================
__device__ __forceinline__ void fullrow16(const float h[8], int cpar, float a[16]) {
    #pragma unroll
    for (int i = 0; i < 8; i++) {
        float o = __shfl_xor_sync(0xffffffffu, h[i], 1);
        a[i]     = cpar ? o    : h[i];
        a[8 + i] = cpar ? h[i] : o;
    }
}

// C(half-row) = a(full row) @ B(smem, stride 20)
__device__ __forceinline__ void wmm16(const float a[16], const float* Bs, int c0, float c[8]) {
    #pragma unroll
    for (int i = 0; i < 8; i++) c[i] = 0.f;
    #pragma unroll
    for (int k = 0; k < 16; k++) {
        float4 b0 = *(const float4*)(Bs + k * 20 + c0);
        float4 b1 = *(const float4*)(Bs + k * 20 + c0 + 4);
        float ak = a[k];
        c[0] += ak * b0.x; c[1] += ak * b0.y; c[2] += ak * b0.z; c[3] += ak * b0.w;
        c[4] += ak * b1.x; c[5] += ak * b1.y; c[6] += ak * b1.z; c[7] += ak * b1.w;
    }
}

// C(half-row) = a(full row) @ B^T (B rows in smem, stride 20)
__device__ __forceinline__ void wmm16t(const float a[16], const float* Bs, int c0, float c[8]) {
    #pragma unroll
    for (int i = 0; i < 8; i++) {
        const float* br = Bs + (c0 + i) * 20;
        float4 b0 = *(const float4*)(br);
        float4 b1 = *(const float4*)(br + 4);
        float4 b2 = *(const float4*)(br + 8);
        float4 b3 = *(const float4*)(br + 12);
        c[i] = a[0]*b0.x + a[1]*b0.y + a[2]*b0.z + a[3]*b0.w
             + a[4]*b1.x + a[5]*b1.y + a[6]*b1.z + a[7]*b1.w
             + a[8]*b2.x + a[9]*b2.y + a[10]*b2.z + a[11]*b2.w
             + a[12]*b3.x + a[13]*b3.y + a[14]*b3.z + a[15]*b3.w;
    }
}

__device__ __forceinline__ void stoh(float* Bs, int r, int c0, const float h[8]) {
    *(float4*)(Bs + r * 20 + c0)     = make_float4(h[0], h[1], h[2], h[3]);
    *(float4*)(Bs + r * 20 + c0 + 4) = make_float4(h[4], h[5], h[6], h[7]);
}

// =====================================================================
// Kernel 0: one-block precompute of batch-invariant matrices (proven)
// =====================================================================
__global__ void precompute_kernel(const float* __restrict__ ref_params,
                                  const float* __restrict__ bias_spd,
                                  const float* __restrict__ bias_gr)
{
    __shared__ float Bs[256], E[256];
    __shared__ float A20[400];
    __shared__ float Aug[20][40];
    __shared__ float prow[40], fcol[20];
    __shared__ float pv;

    const int tid = threadIdx.x;
    const int i = tid >> 4, j = tid & 15;

    // ---- rel = prod of 120 Givens rotations, each lane owns one row ----
    if (tid < 16) {
        float row[16];
        #pragma unroll
        for (int c = 0; c < 16; c++) row[c] = (c == tid) ? 1.f : 0.f;
        int m = 0;
        for (int pi = 0; pi < 16; pi++) {
            for (int pj = pi + 1; pj < 16; pj++) {
                float ang = ref_params[m++];
                float c = cosf(ang), s = sinf(ang);
                float a = row[pi], b = row[pj];
                row[pi] = c * a + s * b;
                row[pj] = -s * a + c * b;
            }
        }
        #pragma unroll
        for (int c = 0; c < 16; c++) g_rel[tid * 16 + c] = row[c];
    }

    // ---- W = expm(-0.25*(bias+bias^T)) via scaling(2^-7) + Taylor-8 ----
    {
        float v = -0.25f * (bias_spd[i * 16 + j] + bias_spd[j * 16 + i]);
        Bs[tid] = v * (1.0f / 128.0f);
        E[tid]  = (i == j) ? 1.f : 0.f;
    }
    __syncthreads();
    for (int k = 8; k >= 1; k--) {
        float a = 0.f;
        #pragma unroll
        for (int kk = 0; kk < 16; kk++) a += Bs[i * 16 + kk] * E[kk * 16 + j];
        __syncthreads();
        E[tid] = ((i == j) ? 1.f : 0.f) + a * (1.0f / (float)k);
        __syncthreads();
    }
    for (int q = 0; q < 7; q++) {
        float a = 0.f;
        #pragma unroll
        for (int kk = 0; kk < 16; kk++) a += E[i * 16 + kk] * E[kk * 16 + j];
        __syncthreads();
        E[tid] = a;
        __syncthreads();
    }
    g_W[tid] = E[tid];

    // ---- Ybg = (I - A)(I + A)^{-1}, A = skew(bias_gr) 20x20 ----
    for (int e = tid; e < 400; e += 256) {
        int ii = e / 20, jj = e % 20;
        float v = 0.f;
        if (ii < 10 && jj >= 10)      v =  bias_gr[ii * 10 + (jj - 10)];
        else if (ii >= 10 && jj < 10) v = -bias_gr[jj * 10 + (ii - 10)];
        A20[e] = v;
    }
    __syncthreads();
    for (int e = tid; e < 800; e += 256) {
        int ii = e / 40, jj = e % 40;
        float v;
        if (jj < 20) v = ((ii == jj) ? 1.f : 0.f) + A20[ii * 20 + jj];
        else         v = ((jj - 20) == ii) ? 1.f : 0.f;
        Aug[ii][jj] = v;
    }
    __syncthreads();
    for (int p = 0; p < 20; p++) {
        if (tid == 0) pv = Aug[p][p];
        __syncthreads();
        if (tid < 40) prow[tid] = Aug[p][tid] / pv;
        if (tid >= 64 && tid < 84) {
            int r = tid - 64;
            fcol[r] = (r == p) ? 0.f : Aug[r][p];
        }
        __syncthreads();
        for (int e = tid; e < 800; e += 256) {
            int ii = e / 40, jj = e % 40;
            Aug[ii][jj] = (ii == p) ? prow[jj] : Aug[ii][jj] - fcol[ii] * prow[jj];
        }
        __syncthreads();
    }
    for (int e = tid; e < 400; e += 256) {
        int ii = e / 20, jj = e % 20;
        float a = 0.f;
        #pragma unroll
        for (int k = 0; k < 20; k++) {
            float l = ((ii == k) ? 1.f : 0.f) - A20[ii * 20 + k];
            a += l * Aug[k][jj + 20];
        }
        g_Ybg[e] = a;
    }
}

// =====================================================================
// Fused kernel: grid = B, block = 64 (2 warps per batch element).
//   warp0: SPD q-chain (P init = Rel)  ->  NS inv-sqrt -> m -> Jacobi -> dspd
//   warp1: SPD a-chain -> Xa to smem  ->  GR chain (both tables) -> dgr
// Combined at the end by warp0 lane 0.
// =====================================================================
__global__ void __launch_bounds__(64)
fused_kernel(const int* __restrict__ q_ids, const int* __restrict__ a_ids,
             const float* __restrict__ q_emb_spd, const float* __restrict__ a_emb_spd,
             const float* __restrict__ q_emb_gr, const float* __restrict__ a_emb_gr,
             const float* __restrict__ trans,
             const float* __restrict__ wf, const float* __restrict__ wb,
             float* __restrict__ out, int B, int T)
{
    __shared__ float buf0[640], buf1[640];
    __shared__ float XaS[320];
    __shared__ float RelS[320], WS[320];
    __shared__ float YbgT[400], transS[100];
    __shared__ float dgr_s;

    const int tid = threadIdx.x;
    for (int e = tid; e < 256; e += 64) {
        RelS[(e >> 4) * 20 + (e & 15)] = g_rel[e];
        WS  [(e >> 4) * 20 + (e & 15)] = g_W[e];
    }
    for (int e = tid; e < 400; e += 64) {
        int ii = e / 20, kk = e - ii * 20;
        YbgT[kk * 20 + ii] = g_Ybg[e];
    }
    for (int e = tid; e < 100; e += 64) transS[e] = trans[e];
    __syncthreads();

    const int w = tid >> 5, lane = tid & 31;
    const int b = blockIdx.x;
    const int r = lane >> 1, cpar = lane & 1, c0 = cpar * 8;
    float* bufA = w ? buf1 : buf0;
    float* bufB = bufA + 320;

    // =============== phase 1: SPD chain, table = w ===============
    const int* ids = w ? a_ids : q_ids;
    const float* emb = w ? a_emb_spd : q_emb_spd;

    float P[8];
    if (w == 0) {
        #pragma unroll
        for (int i = 0; i < 8; i++) P[i] = RelS[r * 20 + c0 + i];   // P = Rel
    } else {
        #pragma unroll
        for (int i = 0; i < 8; i++) P[i] = ((r >> 3) == cpar && (r & 7) == i) ? 1.f : 0.f;
    }

    const int nmid = T - 1;
    #pragma unroll 1
    for (int t = 0; t < nmid; t += 4) {
        float er[8] = {0.f,0.f,0.f,0.f,0.f,0.f,0.f,0.f};
        #pragma unroll
        for (int s = 0; s < 4; s++) {
            int tt = t + s;
            if (tt < nmid) {
                int id = ids[b * T + tt];
                const float* rp = emb + (size_t)id * 256 + r * 16 + c0;
                float4 e0 = *(const float4*)rp;
                float4 e1 = *(const float4*)(rp + 4);
                er[0]+=e0.x; er[1]+=e0.y; er[2]+=e0.z; er[3]+=e0.w;
                er[4]+=e1.x; er[5]+=e1.y; er[6]+=e1.z; er[7]+=e1.w;
            }
        }
        __syncwarp();                                  // prior-iter buf reads done
        stoh(bufA, r, c0, er);
        __syncwarp();                                  // Esum visible
        float Ah[8];
        #pragma unroll
        for (int i = 0; i < 8; i++) Ah[i] = 0.25f * (er[i] + bufA[(c0 + i) * 20 + r]);
        stoh(bufB, r, c0, Ah);
        __syncwarp();                                  // A visible
        float p16[16]; fullrow16(P, cpar, p16);
        float PA[8];  wmm16(p16, bufB, c0, PA);        // P @ sum(A)
        #pragma unroll
        for (int i = 0; i < 8; i++) P[i] += PA[i];
    }

    // last token: Exp = I + A + A^2/2, Y = P @ Exp @ P^T
    float Y[8];
    {
        int id = ids[b * T + (T - 1)];
        const float* rp = emb + (size_t)id * 256 + r * 16 + c0;
        float4 e0 = *(const float4*)rp;
        float4 e1 = *(const float4*)(rp + 4);
        __syncwarp();
        *(float4*)(bufA + r * 20 + c0)     = e0;
        *(float4*)(bufA + r * 20 + c0 + 4) = e1;
        __syncwarp();
        float er[8] = {e0.x, e0.y, e0.z, e0.w, e1.x, e1.y, e1.z, e1.w};
        float Ah[8];
        #pragma unroll
        for (int i = 0; i < 8; i++) Ah[i] = 0.5f * (er[i] + bufA[(c0 + i) * 20 + r]);
        stoh(bufB, r, c0, Ah);
        __syncwarp();
        float a16[16]; fullrow16(Ah, cpar, a16);
        float A2[8];  wmm16(a16, bufB, c0, A2);
        float Sm[8];
        #pragma unroll
        for (int i = 0; i < 8; i++) Sm[i] = Ah[i] + 0.5f * A2[i];
        if ((r >> 3) == cpar) Sm[r & 7] += 1.f;
        __syncwarp();
        stoh(bufB, r, c0, Sm);
        stoh(bufA, r, c0, P);                          // stash P for transpose
        __syncwarp();
        float p16[16]; fullrow16(P, cpar, p16);
        float Pn[8];  wmm16(p16, bufB, c0, Pn);        // P @ Exp
        float t16[16]; fullrow16(Pn, cpar, t16);
        wmm16t(t16, bufA, c0, Y);                      // @ P^T
    }
    if (w == 1) stoh(XaS, r, c0, Y);                   // publish Xa
    __syncthreads();                                   // ---- phase boundary ----

    // =============== phase 2 ===============
    float dspd = 0.f;
    if (w == 0) {
        // ---- Newton-Schulz: Z -> X^{-1/2}  (X = Y, already rel-conjugated) ----
        float Z[8];
        #pragma unroll
        for (int i = 0; i < 8; i++) Z[i] = ((r >> 3) == cpar && (r & 7) == i) ? 1.f : 0.f;
        #pragma unroll 1
        for (int it = 0; it < NS_ITERS; it++) {
            __syncwarp(); stoh(bufA, r, c0, Y); __syncwarp();
            float z16[16]; fullrow16(Z, cpar, z16);
            float G[8];   wmm16(z16, bufA, c0, G);      // Z@Y
            #pragma unroll
            for (int i = 0; i < 8; i++) G[i] = -0.5f * G[i];
            if ((r >> 3) == cpar) G[r & 7] += 1.5f;
            __syncwarp(); stoh(bufB, r, c0, G); __syncwarp();
            float y16[16]; fullrow16(Y, cpar, y16);
            float Yn[8];  wmm16(y16, bufB, c0, Yn);     // Y@G
            __syncwarp(); stoh(bufA, r, c0, Z); __syncwarp();
            float g16[16]; fullrow16(G, cpar, g16);
            float Zn[8];  wmm16(g16, bufA, c0, Zn);     // G@Z
            #pragma unroll
            for (int i = 0; i < 8; i++) { Y[i] = Yn[i]; Z[i] = Zn[i]; }
        }

        // ---- m = C @ Xa @ C^T, C = W@Z (W,Z symmetric) ----
        __syncwarp(); stoh(bufA, r, c0, Z); __syncwarp();
        {
            const float* wr = WS + r * 20;
            float4 w0 = *(const float4*)wr,       w1 = *(const float4*)(wr + 4),
                   w2 = *(const float4*)(wr + 8), w3 = *(const float4*)(wr + 12);
            float wrow[16] = {w0.x,w0.y,w0.z,w0.w, w1.x,w1.y,w1.z,w1.w,
                              w2.x,w2.y,w2.z,w2.w, w3.x,w3.y,w3.z,w3.w};
            float Ch[8]; wmm16(wrow, bufA, c0, Ch);     // C = W@Z
            __syncwarp(); stoh(bufB, r, c0, Ch); __syncwarp();
            float c16[16]; fullrow16(Ch, cpar, c16);
            float T1[8]; wmm16(c16, XaS, c0, T1);       // C@Xa
            float t16[16]; fullrow16(T1, cpar, t16);
            float Mh[8]; wmm16t(t16, bufB, c0, Mh);     // @C^T
            __syncwarp(); stoh(bufA, r, c0, Mh); __syncwarp();
        }

        // ---- shfl-resident Jacobi (rows in registers) ----
        const int jr = lane & 15;
        float a[16];
        {
            const float* rp = bufA + jr * 20;
            float4 v0 = *(const float4*)rp,        v1 = *(const float4*)(rp + 4),
                   v2 = *(const float4*)(rp + 8),  v3 = *(const float4*)(rp + 12);
            a[0]=v0.x; a[1]=v0.y; a[2]=v0.z; a[3]=v0.w;
            a[4]=v1.x; a[5]=v1.y; a[6]=v1.z; a[7]=v1.w;
            a[8]=v2.x; a[9]=v2.y; a[10]=v2.z; a[11]=v2.w;
            a[12]=v3.x; a[13]=v3.y; a[14]=v3.z; a[15]=v3.w;
        }
        #pragma unroll 1
        for (int sweep = 0; sweep < JAC_SWEEPS; sweep++) {
            #pragma unroll
            for (int rr = 0; rr < 15; rr++) {
                int u  = (jr == 0) ? 15 : (jr - 1 - rr + 30) % 15;
                int pu = (u == 15) ? 14 : ((u == 14) ? 15 : 13 - u);
                int partner = (pu == 15) ? 0 : 1 + ((pu + rr) % 15);
                bool isp = (jr == 0) || (u <= 6);
                float mydiag = 0.f, across = 0.f;
                #pragma unroll
                for (int i = 0; i < 16; i++) {
                    if (i == jr)      mydiag = a[i];
                    if (i == partner) across = a[i];
                }
                float partdiag = __shfl_sync(0xffffffffu, mydiag, partner);
                float cc, ss;
                if (fabsf(across) < 1e-30f) { cc = 1.f; ss = 0.f; }
                else {
                    float diff = isp ? (partdiag - mydiag) : (mydiag - partdiag);
                    float tau = diff / (2.f * across);
                    float tt = (tau >= 0.f ? 1.f : -1.f) / (fabsf(tau) + sqrtf(1.f + tau * tau));
                    cc = rsqrtf(1.f + tt * tt); ss = tt * cc;
                }
                float bme = isp ? -ss : ss;
                float nr[16];
                #pragma unroll
                for (int i = 0; i < 16; i++) {
                    float pv = __shfl_sync(0xffffffffu, a[i], partner);
                    nr[i] = cc * a[i] + bme * pv;
                }
                #pragma unroll
                for (int i = 0; i < 16; i++) {
                    int ui  = (i == 0) ? 15 : (i - 1 - rr + 30) % 15;
                    int pui = (ui == 15) ? 14 : ((ui == 14) ? 15 : 13 - ui);
                    int pi_ = (pui == 15) ? 0 : 1 + ((pui + rr) % 15);
                    float ciV = __shfl_sync(0xffffffffu, cc, i);
                    float siV = __shfl_sync(0xffffffffu, ss, i);
                    float biV = ((i == 0) || (ui <= 6)) ? -siV : siV;
                    a[i] = ciV * nr[i] + biV * nr[pi_];
                }
            }
        }
        float acc = 0.f;
        if (lane < 16) {
            float d = 0.f;
            #pragma unroll
            for (int i = 0; i < 16; i++) if (i == jr) d = a[i];
            float l = logf(fmaxf(d, 1e-30f));
            acc = l * l;
        }
        #pragma unroll
        for (int o = 8; o; o >>= 1) acc += __shfl_xor_sync(0xffffffffu, acc, o);
        dspd = sqrtf(acc);
    } else {
        // =============== warp1: Grassmannian chain (both tables) ===============
        float* xw  = buf1;          // 240 floats
        float* q1w = buf1 + 240;    // 200 floats
        const int tbl = lane / 10;
        const int j = lane - tbl * 10;
        const bool active = lane < 20;

        float Mt[10], Mb[10];
        #pragma unroll
        for (int k = 0; k < 10; k++) { Mt[k] = (k == j && active) ? 1.f : 0.f; Mb[k] = 0.f; }

        #pragma unroll 1
        for (int t = T - 1; t >= 0; t--) {
            int qid = q_ids[b * T + t], aid = a_ids[b * T + t];
            __syncwarp();
            for (int e = lane; e < 100; e += 32) {
                int rr = e / 10, cc = e - rr * 10;
                xw[rr * 12 + cc]       = q_emb_gr[(size_t)qid * 100 + e] * transS[e];
                xw[120 + rr * 12 + cc] = a_emb_gr[(size_t)aid * 100 + e];
            }
            __syncwarp();
            if (active) {
                const float* xb = xw + tbl * 120;
                float u[10], v[10], w1[10], w2[10];
                #pragma unroll
                for (int k = 0; k < 10; k++) { v[k] = 0.f; w2[k] = 0.f; }
                #pragma unroll
                for (int k = 0; k < 10; k++) {
                    float4 r0 = *(const float4*)(xb + k * 12);
                    float4 r1 = *(const float4*)(xb + k * 12 + 4);
                    float4 r2 = *(const float4*)(xb + k * 12 + 8);
                    float xr[10] = {r0.x,r0.y,r0.z,r0.w, r1.x,r1.y,r1.z,r1.w, r2.x,r2.y};
                    float s = 0.f;
                    #pragma unroll
                    for (int c = 0; c < 10; c++) s += xr[c] * Mb[c];
                    u[k] = s;
                    float mtk = Mt[k];
                    #pragma unroll
                    for (int c = 0; c < 10; c++) v[c] += mtk * xr[c];
                }
                #pragma unroll
                for (int k = 0; k < 10; k++) {
                    float4 r0 = *(const float4*)(xb + k * 12);
                    float4 r1 = *(const float4*)(xb + k * 12 + 4);
                    float4 r2 = *(const float4*)(xb + k * 12 + 8);
                    float xr[10] = {r0.x,r0.y,r0.z,r0.w, r1.x,r1.y,r1.z,r1.w, r2.x,r2.y};
                    float s = 0.f;
                    #pragma unroll
                    for (int c = 0; c < 10; c++) s += xr[c] * v[c];
                    w1[k] = s;
                    float uk = u[k];
                    #pragma unroll
                    for (int c = 0; c < 10; c++) w2[c] += uk * xr[c];
                }
                #pragma unroll
                for (int k = 0; k < 10; k++) {
                    Mt[k] = Mt[k] - 2.f * u[k] - 2.f * w1[k];
                    Mb[k] = Mb[k] + 2.f * v[k] - 2.f * w2[k];
                }
            }
        }

        // epilogue: dgr
        if (lane < 10) {
            float Q1[20];
            #pragma unroll
            for (int i = 0; i < 20; i++) Q1[i] = 0.f;
            #pragma unroll
            for (int k = 0; k < 20; k++) {
                float ck = (k < 10) ? Mt[k] : Mb[k - 10];
                const float* yr = YbgT + k * 20;
                float4 y0 = *(const float4*)yr,       y1 = *(const float4*)(yr + 4),
                       y2 = *(const float4*)(yr + 8), y3 = *(const float4*)(yr + 12),
                       y4 = *(const float4*)(yr + 16);
                Q1[0]+=ck*y0.x; Q1[1]+=ck*y0.y; Q1[2]+=ck*y0.z; Q1[3]+=ck*y0.w;
                Q1[4]+=ck*y1.x; Q1[5]+=ck*y1.y; Q1[6]+=ck*y1.z; Q1[7]+=ck*y1.w;
                Q1[8]+=ck*y2.x; Q1[9]+=ck*y2.y; Q1[10]+=ck*y2.z; Q1[11]+=ck*y2.w;
                Q1[12]+=ck*y3.x; Q1[13]+=ck*y3.y; Q1[14]+=ck*y3.z; Q1[15]+=ck*y3.w;
                Q1[16]+=ck*y4.x; Q1[17]+=ck*y4.y; Q1[18]+=ck*y4.z; Q1[19]+=ck*y4.w;
            }
            #pragma unroll
            for (int i = 0; i < 20; i += 4)
                *(float4*)(q1w + j * 20 + i) = make_float4(Q1[i], Q1[i+1], Q1[i+2], Q1[i+3]);
        }
        __syncwarp();
        float s_loc = 0.f;
        if (lane >= 10 && lane < 20) {
            #pragma unroll
            for (int i = 0; i < 10; i++) {
                const float* qc = q1w + i * 20;
                float4 a0 = *(const float4*)qc,       a1 = *(const float4*)(qc + 4),
                       a2 = *(const float4*)(qc + 8), a3 = *(const float4*)(qc + 12),
                       a4 = *(const float4*)(qc + 16);
                float qv[20] = {a0.x,a0.y,a0.z,a0.w, a1.x,a1.y,a1.z,a1.w,
                                a2.x,a2.y,a2.z,a2.w, a3.x,a3.y,a3.z,a3.w,
                                a4.x,a4.y,a4.z,a4.w};
                float d = 0.f;
                #pragma unroll
                for (int k = 0; k < 20; k++) d += qv[k] * ((k < 10) ? Mt[k] : Mb[k - 10]);
                s_loc += d * d;
            }
        }
        #pragma unroll
        for (int o = 16; o; o >>= 1) s_loc += __shfl_xor_sync(0xffffffffu, s_loc, o);
        if (lane == 0) dgr_s = sqrtf(fmaxf(20.f - 2.f * s_loc, 0.f));
    }

    __syncthreads();                                   // dgr_s ready
    if (w == 0 && lane == 0)
        out[b] = -wf[0] * (dspd + dgr_s) + wb[0];
}

// =====================================================================
extern "C" void kernel_launch(void* const* d_in, const int* in_sizes, int n_in,
                              void* d_out, int out_size)
{
    const int*   q_ids      = (const int*)  d_in[0];
    const int*   a_ids      = (const int*)  d_in[1];
    const float* q_emb_spd  = (const float*)d_in[2];
    const float* a_emb_spd  = (const float*)d_in[3];
    const float* ref_params = (const float*)d_in[4];
    const float* bias_spd   = (const float*)d_in[5];
    const float* q_emb_gr   = (const float*)d_in[6];
    const float* a_emb_gr   = (const float*)d_in[7];
    const float* trans_gr   = (const float*)d_in[8];
    const float* bias_gr    = (const float*)d_in[9];
    const float* wf         = (const float*)d_in[10];
    const float* wb         = (const float*)d_in[11];
    float* out = (float*)d_out;

    int B = out_size;
    int T = in_sizes[0] / B;

    precompute_kernel<<<1, 256>>>(ref_params, bias_spd, bias_gr);
    fused_kernel<<<B, 64>>>(q_ids, a_ids, q_emb_spd, a_emb_spd,
                            q_emb_gr, a_emb_gr, trans_gr, wf, wb, out, B, T);
}